// round 6
// baseline (speedup 1.0000x reference)
#include <cuda_runtime.h>
#include <math.h>

#define BATCH   1024
#define NT      10
#define PADDED  30
#define DEPTH   4
#define LAYERS  2
#define NHEADS  2
#define NCLS    10

typedef unsigned long long u64;

// g_mats layout (each matrix = 4 float2, row-major 2x2):
//   stem   : [0,120)    (t*4+l)*3+w
//   attn   : [120,600)  (((lay*2+h)*3+g)*4+l)*10+w
//   ffn    : [600,840)  ((lay*10+t)*4+l)*3+w
//   reduce : [840,960)  (t*4+l)*3+w
__device__ float2 g_mats[960 * 4];

// ================= compile-time GF(2) mask tables =================
__host__ __device__ constexpr int parity(unsigned x) {
    int p = 0; while (x) { p ^= (int)(x & 1u); x >>= 1; } return p;
}

struct Masks {
    unsigned pm[DEPTH][NT];
    unsigned am[DEPTH][NT];
    unsigned zm[NT];
};

__host__ __device__ constexpr Masks make_masks() {
    Masks M{};
    for (int l = 0; l < DEPTH; l++) {
        unsigned R[NT]{}, Ri[NT]{};
        for (int u = 0; u < NT; u++) { R[u] = 1u << u; Ri[u] = 1u << u; }
        for (int ll = 0; ll < l; ll++) {
            int r = ll + 1;
            for (int i = 0; i < NT; i++) R[(i + r) % NT] ^= R[i];
        }
        for (int ll = l - 1; ll >= 0; ll--) {
            int r = ll + 1;
            for (int i = NT - 1; i >= 0; i--) Ri[(i + r) % NT] ^= Ri[i];
        }
        for (int w = 0; w < NT; w++) {
            unsigned m = 0;
            for (int u = 0; u < NT; u++) if ((Ri[u] >> w) & 1u) m |= 1u << u;
            M.pm[l][w] = m;
            M.am[l][w] = R[w];
        }
    }
    unsigned R[NT]{};
    for (int u = 0; u < NT; u++) R[u] = 1u << u;
    for (int ll = 0; ll < DEPTH; ll++) {
        int r = ll + 1;
        for (int i = 0; i < NT; i++) R[(i + r) % NT] ^= R[i];
    }
    for (int w = 0; w < NT; w++) M.zm[w] = R[w];
    return M;
}

struct Masks2 {
    unsigned pm[3][NT];
    unsigned am[3][NT];
    unsigned zm[NT];
    int posq[NT];
};

__host__ __device__ constexpr Masks2 make_masks2() {
    Masks M = make_masks();
    unsigned bestS = 0x1Fu; int bestScore = -1;
    for (unsigned S = 0; S < 1024u; S++) {
        int pc = 0;
        for (int q = 0; q < NT; q++) pc += (int)((S >> q) & 1u);
        if (pc != 5) continue;
        int score = 0;
        for (int l = 1; l < DEPTH; l++)
            for (int w = 0; w < NT; w++)
                if ((M.pm[l][w] & ~S & 0x3FFu) == 0u) score++;
        if (score > bestScore) { bestScore = score; bestS = S; }
    }
    int qpos[NT]{};
    Masks2 R{};
    {
        int lp = 0, hp = 5;
        for (int q = 0; q < NT; q++) {
            int p = ((bestS >> q) & 1u) ? lp++ : hp++;
            qpos[q] = p;
        }
        for (int q = 0; q < NT; q++) R.posq[qpos[q]] = q;
    }
    for (int l = 1; l < DEPTH; l++)
        for (int w = 0; w < NT; w++) {
            unsigned pm2 = 0, am2 = 0;
            for (int q = 0; q < NT; q++) {
                if ((M.pm[l][w] >> q) & 1u) pm2 |= 1u << qpos[q];
                if ((M.am[l][w] >> q) & 1u) am2 |= 1u << qpos[q];
            }
            R.pm[l - 1][w] = pm2;
            R.am[l - 1][w] = am2;
        }
    for (int w = 0; w < NT; w++) {
        unsigned z2 = 0;
        for (int q = 0; q < NT; q++) if ((M.zm[w] >> q) & 1u) z2 |= 1u << qpos[q];
        R.zm[w] = z2;
    }
    return R;
}
constexpr Masks2 MK2 = make_masks2();

// ================= packed f32x2 complex helpers =================
__device__ __forceinline__ u64 pack2(float lo, float hi) {
    u64 r; asm("mov.b64 %0, {%1,%2};" : "=l"(r) : "f"(lo), "f"(hi)); return r;
}
__device__ __forceinline__ float2 unpack2(u64 a) {
    float2 f; asm("mov.b64 {%0,%1}, %2;" : "=f"(f.x), "=f"(f.y) : "l"(a)); return f;
}
__device__ __forceinline__ u64 swap2(u64 a) {
    u64 r; asm("{ .reg .b32 lo, hi; mov.b64 {lo,hi}, %1; mov.b64 %0, {hi,lo}; }" : "=l"(r) : "l"(a)); return r;
}
__device__ __forceinline__ u64 f2fma(u64 a, u64 b, u64 c) {
    u64 r; asm("fma.rn.f32x2 %0, %1, %2, %3;" : "=l"(r) : "l"(a), "l"(b), "l"(c)); return r;
}
__device__ __forceinline__ u64 f2mul(u64 a, u64 b) {
    u64 r; asm("mul.rn.f32x2 %0, %1, %2;" : "=l"(r) : "l"(a), "l"(b)); return r;
}
__device__ __forceinline__ u64 shfl64_xor(u64 v, int m) {
    unsigned lo = (unsigned)v, hi = (unsigned)(v >> 32);
    lo = __shfl_xor_sync(0xffffffffu, lo, m);
    hi = __shfl_xor_sync(0xffffffffu, hi, m);
    return ((u64)hi << 32) | lo;
}

__device__ __forceinline__ u64 cmix(u64 A, u64 As, u64 B, u64 Bs,
                                    u64 oxx, u64 oyy, u64 txx, u64 tyy) {
    return f2fma(oxx, A, f2fma(oyy, As, f2fma(txx, B, f2mul(tyy, Bs))));
}

__device__ __forceinline__ float2 cmulf(float2 a, float2 b) {
    return make_float2(a.x * b.x - a.y * b.y, a.x * b.y + a.y * b.x);
}

// ================= gate application (all indices compile-time) =================
template<unsigned MLO, unsigned ALO, int J>
__device__ __forceinline__ void local_loop(u64* st, u64 oxx, u64 tyy,
                                           u64 oyy0, u64 oyy1, u64 txx0, u64 txx1) {
    if constexpr (J < 32) {
        constexpr unsigned LOW = MLO & (0u - MLO);
        if constexpr ((J & (int)LOW) == 0) {
            constexpr int J2 = J ^ (int)MLO;
            constexpr int P  = parity(ALO & (unsigned)J);
            constexpr int P2 = parity(ALO & (unsigned)J2);
            u64 A = st[J], B = st[J2];
            u64 As = swap2(A), Bs = swap2(B);
            st[J]  = cmix(A, As, B, Bs, oxx, P  ? oyy1 : oyy0, P  ? txx1 : txx0, tyy);
            st[J2] = cmix(B, Bs, A, As, oxx, P2 ? oyy1 : oyy0, P2 ? txx1 : txx0, tyy);
        }
        local_loop<MLO, ALO, J + 1>(st, oxx, tyy, oyy0, oyy1, txx0, txx1);
    }
}

template<unsigned MHI, unsigned ALO, int J>
__device__ __forceinline__ void lane_loop(u64* st, u64 oxx, u64 tyy,
                                          u64 oyy0, u64 oyy1, u64 txx0, u64 txx1) {
    if constexpr (J < 32) {
        constexpr int P = parity(ALO & (unsigned)J);
        u64 A = st[J];
        u64 B = shfl64_xor(A, (int)MHI);
        u64 As = swap2(A), Bs = swap2(B);
        st[J] = cmix(A, As, B, Bs, oxx, P ? oyy1 : oyy0, P ? txx1 : txx0, tyy);
        lane_loop<MHI, ALO, J + 1>(st, oxx, tyy, oyy0, oyy1, txx0, txx1);
    }
}

template<unsigned MLO, unsigned MHI, unsigned ALO, int J>
__device__ __forceinline__ void mixed_loop(u64* st, u64 oxx, u64 tyy,
                                           u64 oyy0, u64 oyy1, u64 txx0, u64 txx1) {
    if constexpr (J < 32) {
        constexpr unsigned LOW = MLO & (0u - MLO);
        if constexpr ((J & (int)LOW) == 0) {
            constexpr int J2 = J ^ (int)MLO;
            constexpr int P  = parity(ALO & (unsigned)J);
            constexpr int P2 = parity(ALO & (unsigned)J2);
            u64 A = st[J], B = st[J2];
            u64 pA = shfl64_xor(B, (int)MHI);
            u64 pB = shfl64_xor(A, (int)MHI);
            u64 As = swap2(A), Bs = swap2(B), pAs = swap2(pA), pBs = swap2(pB);
            st[J]  = cmix(A, As, pA, pAs, oxx, P  ? oyy1 : oyy0, P  ? txx1 : txx0, tyy);
            st[J2] = cmix(B, Bs, pB, pBs, oxx, P2 ? oyy1 : oyy0, P2 ? txx1 : txx0, tyy);
        }
        mixed_loop<MLO, MHI, ALO, J + 1>(st, oxx, tyy, oyy0, oyy1, txx0, txx1);
    }
}

template<int L, int W>
__device__ __forceinline__ void apply_gate(u64* st, const float2* __restrict__ gm, int lane) {
    constexpr unsigned m   = MK2.pm[L][W];
    constexpr unsigned a   = MK2.am[L][W];
    constexpr unsigned mlo = m & 31u, mhi = (m >> 5) & 31u;
    constexpr unsigned alo = a & 31u, ahi = (a >> 5) & 31u;
    float2 g00 = gm[((L + 1) * 10 + W) * 4 + 0];
    float2 g01 = gm[((L + 1) * 10 + W) * 4 + 1];
    u64 oxx = pack2(g00.x, g00.x);
    u64 oyy = pack2(-g00.y, g00.y);
    u64 txx = pack2(g01.x, g01.x);
    u64 tyy = pack2(-g01.y, g01.y);
    constexpr u64 SGN = 0x8000000080000000ull;
    u64 oyyN = oyy ^ SGN;
    u64 txxN = txx ^ SGN;
    int plane = (int)(__popc(ahi & (unsigned)lane) & 1);
    u64 oyy0 = plane ? oyyN : oyy;
    u64 oyy1 = plane ? oyy  : oyyN;
    u64 txx0 = plane ? txxN : txx;
    u64 txx1 = plane ? txx  : txxN;
    if constexpr (mhi == 0u) {
        local_loop<mlo, alo, 0>(st, oxx, tyy, oyy0, oyy1, txx0, txx1);
    } else if constexpr (mlo == 0u) {
        lane_loop<mhi, alo, 0>(st, oxx, tyy, oyy0, oyy1, txx0, txx1);
    } else {
        mixed_loop<mlo, mhi, alo, 0>(st, oxx, tyy, oyy0, oyy1, txx0, txx1);
    }
}

template<int G>
__device__ __forceinline__ void run_gates(u64* st, const float2* __restrict__ gm, int lane) {
    if constexpr (G < 3 * NT) {
        apply_gate<G / NT, G % NT>(st, gm, lane);
        run_gates<G + 1>(st, gm, lane);
    }
}

// ================= measurement (parity masks) =================
template<unsigned ZLO, int J>
__device__ __forceinline__ void sum_loop(const float* pr, float& acc) {
    if constexpr (J < 32) {
        if constexpr (parity(ZLO & (unsigned)J)) acc -= pr[J]; else acc += pr[J];
        sum_loop<ZLO, J + 1>(pr, acc);
    }
}
template<int W>
__device__ __forceinline__ void meas_from(const float* pr, float* res, int lane) {
    if constexpr (W < NT) {
        constexpr unsigned z = MK2.zm[W];
        constexpr unsigned zlo = z & 31u, zhi = (z >> 5) & 31u;
        float acc = 0.f;
        sum_loop<zlo, 0>(pr, acc);
        int sl = (int)(__popc(zhi & (unsigned)lane) & 1);
        res[W] = sl ? -acc : acc;
        meas_from<W + 1>(pr, res, lane);
    }
}

// compile-time posq gather of embedding factors into position order
template<int P>
__device__ __forceinline__ void gather_factors(float2* fa, float2* fb, float2 va, float2 vb) {
    if constexpr (P < NT) {
        constexpr int q = MK2.posq[P];
        fa[P].x = __shfl_sync(0xffffffffu, va.x, q);
        fa[P].y = __shfl_sync(0xffffffffu, va.y, q);
        fb[P].x = __shfl_sync(0xffffffffu, vb.x, q);
        fb[P].y = __shfl_sync(0xffffffffu, vb.y, q);
        gather_factors<P + 1>(fa, fb, va, vb);
    }
}

// ================= 3-qubit register circuit =================
__device__ __forceinline__ float2 cmul3(float2 a, float2 b) {
    return make_float2(a.x * b.x - a.y * b.y, a.x * b.y + a.y * b.x);
}
__device__ __forceinline__ float2 cadd3(float2 a, float2 b) {
    return make_float2(a.x + b.x, a.y + b.y);
}
__device__ __forceinline__ void run3(float x0, float x1, float x2,
                                     const float2* __restrict__ M, float E[3]) {
    float c[3], s[3];
    __sincosf(0.5f * x0, &s[0], &c[0]);
    __sincosf(0.5f * x1, &s[1], &c[1]);
    __sincosf(0.5f * x2, &s[2], &c[2]);
    float2 a[8];
#pragma unroll
    for (int i = 0; i < 8; i++) {
        float v = ((i >> 2) & 1 ? s[0] : c[0]) *
                  ((i >> 1) & 1 ? s[1] : c[1]) *
                  ((i      ) & 1 ? s[2] : c[2]);
        a[i] = make_float2(v, 0.f);
    }
#pragma unroll
    for (int l = 0; l < 4; l++) {
#pragma unroll
        for (int w = 0; w < 3; w++) {
            const float2* m = M + (l * 3 + w) * 4;
            const int p = 2 - w;
#pragma unroll
            for (int i0 = 0; i0 < 8; i0++) {
                if (i0 & (1 << p)) continue;
                int i1 = i0 | (1 << p);
                float2 A = a[i0], B = a[i1];
                a[i0] = cadd3(cmul3(m[0], A), cmul3(m[1], B));
                a[i1] = cadd3(cmul3(m[2], A), cmul3(m[3], B));
            }
        }
        const int r = (l & 1) + 1;
#pragma unroll
        for (int i = 0; i < 3; i++) {
            int pc = 2 - i;
            int pt = 2 - ((i + r) % 3);
#pragma unroll
            for (int idx = 0; idx < 8; idx++) {
                if (((idx >> pc) & 1) && !((idx >> pt) & 1)) {
                    int j = idx | (1 << pt);
                    float2 t = a[idx]; a[idx] = a[j]; a[j] = t;
                }
            }
        }
    }
    E[0] = E[1] = E[2] = 0.f;
#pragma unroll
    for (int i = 0; i < 8; i++) {
        float p = a[i].x * a[i].x + a[i].y * a[i].y;
        E[0] += (i & 4) ? -p : p;
        E[1] += (i & 2) ? -p : p;
        E[2] += (i & 1) ? -p : p;
    }
}

// ================= prep: Rot matrices =================
__global__ void prep_kernel(const float* __restrict__ t_stem,
                            const float* __restrict__ t_attn,
                            const float* __restrict__ t_ffn,
                            const float* __restrict__ t_red) {
    int i = blockIdx.x * blockDim.x + threadIdx.x;
    if (i < 960) {
        const float* a;
        if (i < 120)      a = t_stem + i * 3;
        else if (i < 600) a = t_attn + (i - 120) * 3;
        else if (i < 840) a = t_ffn  + (i - 600) * 3;
        else              a = t_red  + (i - 840) * 3;
        float phi = a[0], th = a[1], om = a[2];
        float c, s, cp, sp, cm, sm;
        sincosf(0.5f * th, &s, &c);
        sincosf(0.5f * (phi + om), &sp, &cp);
        sincosf(0.5f * (phi - om), &sm, &cm);
        float2* m = &g_mats[i * 4];
        m[0] = make_float2( cp * c, -sp * c);
        m[1] = make_float2(-cm * s, -sm * s);
        m[2] = make_float2( cm * s, -sm * s);
        m[3] = make_float2( cp * c,  sp * c);
    }
}

// ================= fused whole-network kernel: one block per batch element ======
__global__ void __launch_bounds__(192) fused_kernel(const float* __restrict__ x,
                                                    const float* __restrict__ W_O,
                                                    const float* __restrict__ Wc,
                                                    const float* __restrict__ bc,
                                                    float* __restrict__ out) {
    __shared__ float H_s[PADDED];
    __shared__ float attn_s[PADDED * NHEADS];
    __shared__ float newH_s[PADDED];
    __shared__ float red_s[NT];

    const int tid  = threadIdx.x;
    const int wrp  = tid >> 5;          // 0..5
    const int lane = tid & 31;
    const int b    = blockIdx.x;
    const int h    = wrp / 3, g = wrp % 3;

    // ---- stem: token t = wrp + 6*lane (lane<2) ----
    {
        int t = wrp + 6 * lane;
        if (lane < 2 && t < NT) {
            float E[3];
            run3(x[b * 30 + 3 * t], x[b * 30 + 3 * t + 1], x[b * 30 + 3 * t + 2],
                 g_mats + (t * 12) * 4, E);
            H_s[3 * t + 0] = E[0];
            H_s[3 * t + 1] = E[1];
            H_s[3 * t + 2] = E[2];
        }
    }
    __syncthreads();

#pragma unroll
    for (int lay = 0; lay < LAYERS; lay++) {
        // ---- attention: one warp per (h,g) instance ----
        const float2* gm = g_mats + (120 + ((lay * 2 + h) * 3 + g) * 40) * 4;
        {
            float2 va, vb;
            {
                int q = (lane < NT) ? lane : 0;
                float ang = (lane < NT) ? H_s[3 * lane + g] : 0.f;
                float c, s;
                __sincosf(0.5f * ang, &s, &c);
                float2 g00 = gm[q * 4 + 0];
                float2 g01 = gm[q * 4 + 1];
                va = make_float2( g00.x * c + g01.x * s,  g00.y * c + g01.y * s);
                vb = make_float2(-g01.x * c + g00.x * s,  g01.y * c - g00.y * s);
            }
            float2 fa[NT], fb[NT];
            gather_factors<0>(fa, fb, va, vb);
            float2 lf = (lane & 1) ? fb[5] : fa[5];
#pragma unroll
            for (int p = 6; p < NT; p++)
                lf = cmulf(lf, ((lane >> (p - 5)) & 1) ? fb[p] : fa[p]);
            float2 T[32];
            T[0] = cmulf(lf, fa[0]);
            T[1] = cmulf(lf, fb[0]);
#pragma unroll
            for (int k = 1; k < 5; k++) {
#pragma unroll
                for (int j = 0; j < 16; j++) {
                    if (j < (1 << k)) {
                        T[j | (1 << k)] = cmulf(T[j], fb[k]);
                        T[j]            = cmulf(T[j], fa[k]);
                    }
                }
            }
            u64 st[32];
#pragma unroll
            for (int j = 0; j < 32; j++) st[j] = pack2(T[j].x, T[j].y);

            run_gates<0>(st, gm, lane);

            float pr[32];
#pragma unroll
            for (int j = 0; j < 32; j++) {
                float2 f = unpack2(st[j]);
                pr[j] = f.x * f.x + f.y * f.y;
            }
            float res[NT];
            meas_from<0>(pr, res, lane);
#pragma unroll
            for (int w = 0; w < NT; w++) {
#pragma unroll
                for (int off = 16; off; off >>= 1)
                    res[w] += __shfl_xor_sync(0xffffffffu, res[w], off);
            }
            if (lane == 0) {
#pragma unroll
                for (int w = 0; w < NT; w++)
                    attn_s[h * 30 + 3 * w + g] = res[w];
            }
        }
        __syncthreads();

        // ---- W_O projection + residual: output j = wrp + 6*lane (lane<5) ----
        if (lane < 5) {
            int j = wrp + 6 * lane;
            const float* wrow = W_O + (lay * 30 + j) * 60;
            float s0 = 0.f, s1 = 0.f;
#pragma unroll
            for (int k = 0; k < 60; k += 2) {
                s0 = fmaf(attn_s[k],     wrow[k],     s0);
                s1 = fmaf(attn_s[k + 1], wrow[k + 1], s1);
            }
            newH_s[j] = H_s[j] + s0 + s1;
        }
        __syncthreads();

        // ---- FFN: token t = wrp + 6*lane (lane<2) ----
        {
            int t = wrp + 6 * lane;
            if (lane < 2 && t < NT) {
                float in[3];
#pragma unroll
                for (int j = 0; j < 3; j++) {
                    int f = 3 * t + j;
                    in[j] = newH_s[3 * (f % 10) + f / 10];
                }
                float E[3];
                run3(in[0], in[1], in[2], g_mats + (600 + (lay * 10 + t) * 12) * 4, E);
                H_s[3 * t + 0] = newH_s[3 * t + 0] + E[0];
                H_s[3 * t + 1] = newH_s[3 * t + 1] + E[1];
                H_s[3 * t + 2] = newH_s[3 * t + 2] + E[2];
            }
        }
        __syncthreads();
    }

    // ---- reduce: token t = wrp + 6*lane (lane<2) ----
    {
        int t = wrp + 6 * lane;
        if (lane < 2 && t < NT) {
            float E[3];
            run3(H_s[3 * t], H_s[3 * t + 1], H_s[3 * t + 2],
                 g_mats + (840 + t * 12) * 4, E);
            red_s[t] = E[0];
        }
    }
    __syncthreads();

    // ---- classification: class c = wrp + 6*lane (lane<2) ----
    {
        int c = wrp + 6 * lane;
        if (lane < 2 && c < NCLS) {
            float s = bc[c];
#pragma unroll
            for (int t = 0; t < NT; t++)
                s = fmaf(red_s[t], Wc[c * 10 + t], s);
            out[b * 10 + c] = s;
        }
    }
}

// ================= launch =================
extern "C" void kernel_launch(void* const* d_in, const int* in_sizes, int n_in,
                              void* d_out, int out_size) {
    const float* x_      = (const float*)d_in[0];
    const float* t_stem  = (const float*)d_in[1];
    const float* t_attn  = (const float*)d_in[2];
    const float* W_O     = (const float*)d_in[3];
    const float* t_ffn   = (const float*)d_in[4];
    const float* t_red   = (const float*)d_in[5];
    const float* W_cls   = (const float*)d_in[6];
    const float* b_cls   = (const float*)d_in[7];
    float* out = (float*)d_out;

    prep_kernel<<<4, 256>>>(t_stem, t_attn, t_ffn, t_red);
    fused_kernel<<<BATCH, 192>>>(x_, W_O, W_cls, b_cls, out);
}

// round 7
// speedup vs baseline: 1.1528x; 1.1528x over previous
#include <cuda_runtime.h>
#include <math.h>

#define BATCH   1024
#define NT      10
#define PADDED  30
#define DEPTH   4
#define LAYERS  2
#define NHEADS  2
#define NCLS    10

typedef unsigned long long u64;

// g_mats layout (each matrix = 4 float2, row-major 2x2):
//   stem   : [0,120)    (t*4+l)*3+w
//   attn   : [120,600)  (((lay*2+h)*3+g)*4+l)*10+w
//   ffn    : [600,840)  ((lay*10+t)*4+l)*3+w
//   reduce : [840,960)  (t*4+l)*3+w
__device__ float2 g_mats[960 * 4];
__device__ float  g_H[BATCH * PADDED];
__device__ float  g_attn[BATCH * PADDED * NHEADS];

// ================= compile-time GF(2) mask tables =================
__host__ __device__ constexpr int parity(unsigned x) {
    int p = 0; while (x) { p ^= (int)(x & 1u); x >>= 1; } return p;
}

struct Masks {
    unsigned pm[DEPTH][NT];
    unsigned am[DEPTH][NT];
    unsigned zm[NT];
};

__host__ __device__ constexpr Masks make_masks() {
    Masks M{};
    for (int l = 0; l < DEPTH; l++) {
        unsigned R[NT]{}, Ri[NT]{};
        for (int u = 0; u < NT; u++) { R[u] = 1u << u; Ri[u] = 1u << u; }
        for (int ll = 0; ll < l; ll++) {
            int r = ll + 1;
            for (int i = 0; i < NT; i++) R[(i + r) % NT] ^= R[i];
        }
        for (int ll = l - 1; ll >= 0; ll--) {
            int r = ll + 1;
            for (int i = NT - 1; i >= 0; i--) Ri[(i + r) % NT] ^= Ri[i];
        }
        for (int w = 0; w < NT; w++) {
            unsigned m = 0;
            for (int u = 0; u < NT; u++) if ((Ri[u] >> w) & 1u) m |= 1u << u;
            M.pm[l][w] = m;
            M.am[l][w] = R[w];
        }
    }
    unsigned R[NT]{};
    for (int u = 0; u < NT; u++) R[u] = 1u << u;
    for (int ll = 0; ll < DEPTH; ll++) {
        int r = ll + 1;
        for (int i = 0; i < NT; i++) R[(i + r) % NT] ^= R[i];
    }
    for (int w = 0; w < NT; w++) M.zm[w] = R[w];
    return M;
}

struct Masks2 {
    unsigned pm[3][NT];
    unsigned am[3][NT];
    unsigned zm[NT];
    int posq[NT];
};

__host__ __device__ constexpr Masks2 make_masks2() {
    Masks M = make_masks();
    unsigned bestS = 0x1Fu; int bestScore = -1;
    for (unsigned S = 0; S < 1024u; S++) {
        int pc = 0;
        for (int q = 0; q < NT; q++) pc += (int)((S >> q) & 1u);
        if (pc != 5) continue;
        int score = 0;
        for (int l = 1; l < DEPTH; l++)
            for (int w = 0; w < NT; w++)
                if ((M.pm[l][w] & ~S & 0x3FFu) == 0u) score++;
        if (score > bestScore) { bestScore = score; bestS = S; }
    }
    int qpos[NT]{};
    Masks2 R{};
    {
        int lp = 0, hp = 5;
        for (int q = 0; q < NT; q++) {
            int p = ((bestS >> q) & 1u) ? lp++ : hp++;
            qpos[q] = p;
        }
        for (int q = 0; q < NT; q++) R.posq[qpos[q]] = q;
    }
    for (int l = 1; l < DEPTH; l++)
        for (int w = 0; w < NT; w++) {
            unsigned pm2 = 0, am2 = 0;
            for (int q = 0; q < NT; q++) {
                if ((M.pm[l][w] >> q) & 1u) pm2 |= 1u << qpos[q];
                if ((M.am[l][w] >> q) & 1u) am2 |= 1u << qpos[q];
            }
            R.pm[l - 1][w] = pm2;
            R.am[l - 1][w] = am2;
        }
    for (int w = 0; w < NT; w++) {
        unsigned z2 = 0;
        for (int q = 0; q < NT; q++) if ((M.zm[w] >> q) & 1u) z2 |= 1u << qpos[q];
        R.zm[w] = z2;
    }
    return R;
}
constexpr Masks2 MK2 = make_masks2();

// ================= packed f32x2 complex helpers =================
__device__ __forceinline__ u64 pack2(float lo, float hi) {
    u64 r; asm("mov.b64 %0, {%1,%2};" : "=l"(r) : "f"(lo), "f"(hi)); return r;
}
__device__ __forceinline__ float2 unpack2(u64 a) {
    float2 f; asm("mov.b64 {%0,%1}, %2;" : "=f"(f.x), "=f"(f.y) : "l"(a)); return f;
}
__device__ __forceinline__ u64 swap2(u64 a) {
    u64 r; asm("{ .reg .b32 lo, hi; mov.b64 {lo,hi}, %1; mov.b64 %0, {hi,lo}; }" : "=l"(r) : "l"(a)); return r;
}
__device__ __forceinline__ u64 f2fma(u64 a, u64 b, u64 c) {
    u64 r; asm("fma.rn.f32x2 %0, %1, %2, %3;" : "=l"(r) : "l"(a), "l"(b), "l"(c)); return r;
}
__device__ __forceinline__ u64 f2mul(u64 a, u64 b) {
    u64 r; asm("mul.rn.f32x2 %0, %1, %2;" : "=l"(r) : "l"(a), "l"(b)); return r;
}
__device__ __forceinline__ u64 shfl64_xor(u64 v, int m) {
    unsigned lo = (unsigned)v, hi = (unsigned)(v >> 32);
    lo = __shfl_xor_sync(0xffffffffu, lo, m);
    hi = __shfl_xor_sync(0xffffffffu, hi, m);
    return ((u64)hi << 32) | lo;
}

__device__ __forceinline__ u64 cmix(u64 A, u64 As, u64 B, u64 Bs,
                                    u64 oxx, u64 oyy, u64 txx, u64 tyy) {
    return f2fma(oxx, A, f2fma(oyy, As, f2fma(txx, B, f2mul(tyy, Bs))));
}

__device__ __forceinline__ float2 cmulf(float2 a, float2 b) {
    return make_float2(a.x * b.x - a.y * b.y, a.x * b.y + a.y * b.x);
}

// ================= gate application (all indices compile-time) =================
template<unsigned MLO, unsigned ALO, int J>
__device__ __forceinline__ void local_loop(u64* st, u64 oxx, u64 tyy,
                                           u64 oyy0, u64 oyy1, u64 txx0, u64 txx1) {
    if constexpr (J < 32) {
        constexpr unsigned LOW = MLO & (0u - MLO);
        if constexpr ((J & (int)LOW) == 0) {
            constexpr int J2 = J ^ (int)MLO;
            constexpr int P  = parity(ALO & (unsigned)J);
            constexpr int P2 = parity(ALO & (unsigned)J2);
            u64 A = st[J], B = st[J2];
            u64 As = swap2(A), Bs = swap2(B);
            st[J]  = cmix(A, As, B, Bs, oxx, P  ? oyy1 : oyy0, P  ? txx1 : txx0, tyy);
            st[J2] = cmix(B, Bs, A, As, oxx, P2 ? oyy1 : oyy0, P2 ? txx1 : txx0, tyy);
        }
        local_loop<MLO, ALO, J + 1>(st, oxx, tyy, oyy0, oyy1, txx0, txx1);
    }
}

template<unsigned MHI, unsigned ALO, int J>
__device__ __forceinline__ void lane_loop(u64* st, u64 oxx, u64 tyy,
                                          u64 oyy0, u64 oyy1, u64 txx0, u64 txx1) {
    if constexpr (J < 32) {
        constexpr int P = parity(ALO & (unsigned)J);
        u64 A = st[J];
        u64 B = shfl64_xor(A, (int)MHI);
        u64 As = swap2(A), Bs = swap2(B);
        st[J] = cmix(A, As, B, Bs, oxx, P ? oyy1 : oyy0, P ? txx1 : txx0, tyy);
        lane_loop<MHI, ALO, J + 1>(st, oxx, tyy, oyy0, oyy1, txx0, txx1);
    }
}

template<unsigned MLO, unsigned MHI, unsigned ALO, int J>
__device__ __forceinline__ void mixed_loop(u64* st, u64 oxx, u64 tyy,
                                           u64 oyy0, u64 oyy1, u64 txx0, u64 txx1) {
    if constexpr (J < 32) {
        constexpr unsigned LOW = MLO & (0u - MLO);
        if constexpr ((J & (int)LOW) == 0) {
            constexpr int J2 = J ^ (int)MLO;
            constexpr int P  = parity(ALO & (unsigned)J);
            constexpr int P2 = parity(ALO & (unsigned)J2);
            u64 A = st[J], B = st[J2];
            u64 pA = shfl64_xor(B, (int)MHI);
            u64 pB = shfl64_xor(A, (int)MHI);
            u64 As = swap2(A), Bs = swap2(B), pAs = swap2(pA), pBs = swap2(pB);
            st[J]  = cmix(A, As, pA, pAs, oxx, P  ? oyy1 : oyy0, P  ? txx1 : txx0, tyy);
            st[J2] = cmix(B, Bs, pB, pBs, oxx, P2 ? oyy1 : oyy0, P2 ? txx1 : txx0, tyy);
        }
        mixed_loop<MLO, MHI, ALO, J + 1>(st, oxx, tyy, oyy0, oyy1, txx0, txx1);
    }
}

template<int L, int W>
__device__ __forceinline__ void apply_gate(u64* st, const float2* __restrict__ gm, int lane) {
    constexpr unsigned m   = MK2.pm[L][W];
    constexpr unsigned a   = MK2.am[L][W];
    constexpr unsigned mlo = m & 31u, mhi = (m >> 5) & 31u;
    constexpr unsigned alo = a & 31u, ahi = (a >> 5) & 31u;
    float2 g00 = gm[((L + 1) * 10 + W) * 4 + 0];
    float2 g01 = gm[((L + 1) * 10 + W) * 4 + 1];
    u64 oxx = pack2(g00.x, g00.x);
    u64 oyy = pack2(-g00.y, g00.y);
    u64 txx = pack2(g01.x, g01.x);
    u64 tyy = pack2(-g01.y, g01.y);
    constexpr u64 SGN = 0x8000000080000000ull;
    u64 oyyN = oyy ^ SGN;
    u64 txxN = txx ^ SGN;
    int plane = (int)(__popc(ahi & (unsigned)lane) & 1);
    u64 oyy0 = plane ? oyyN : oyy;
    u64 oyy1 = plane ? oyy  : oyyN;
    u64 txx0 = plane ? txxN : txx;
    u64 txx1 = plane ? txx  : txxN;
    if constexpr (mhi == 0u) {
        local_loop<mlo, alo, 0>(st, oxx, tyy, oyy0, oyy1, txx0, txx1);
    } else if constexpr (mlo == 0u) {
        lane_loop<mhi, alo, 0>(st, oxx, tyy, oyy0, oyy1, txx0, txx1);
    } else {
        mixed_loop<mlo, mhi, alo, 0>(st, oxx, tyy, oyy0, oyy1, txx0, txx1);
    }
}

template<int G>
__device__ __forceinline__ void run_gates(u64* st, const float2* __restrict__ gm, int lane) {
    if constexpr (G < 3 * NT) {
        apply_gate<G / NT, G % NT>(st, gm, lane);
        run_gates<G + 1>(st, gm, lane);
    }
}

// ================= incremental measurement (no pr array) =================
template<int J, int W>
__device__ __forceinline__ void acc_w(float p, float* res) {
    if constexpr (W < NT) {
        constexpr unsigned zlo = MK2.zm[W] & 31u;
        if constexpr (parity(zlo & (unsigned)J)) res[W] -= p; else res[W] += p;
        acc_w<J, W + 1>(p, res);
    }
}
template<int J>
__device__ __forceinline__ void meas_loop(const u64* st, float* res) {
    if constexpr (J < 32) {
        float2 f = unpack2(st[J]);
        float p = f.x * f.x + f.y * f.y;
        acc_w<J, 0>(p, res);
        meas_loop<J + 1>(st, res);
    }
}
template<int W>
__device__ __forceinline__ void lane_sign(float* res, int lane) {
    if constexpr (W < NT) {
        constexpr unsigned zhi = (MK2.zm[W] >> 5) & 31u;
        if ((int)(__popc(zhi & (unsigned)lane) & 1)) res[W] = -res[W];
        lane_sign<W + 1>(res, lane);
    }
}

// fetch embedding factor for position P (compile-time shuffle source)
template<int P>
__device__ __forceinline__ void fetch_f(float2 va, float2 vb, float2& fa, float2& fb) {
    constexpr int q = MK2.posq[P];
    fa.x = __shfl_sync(0xffffffffu, va.x, q);
    fa.y = __shfl_sync(0xffffffffu, va.y, q);
    fb.x = __shfl_sync(0xffffffffu, vb.x, q);
    fb.y = __shfl_sync(0xffffffffu, vb.y, q);
}

// lane factor: product over positions 5..9 selected by lane bits 0..4
template<int I>
__device__ __forceinline__ float2 lf_step(float2 va, float2 vb, int lane, float2 cur) {
    if constexpr (I < 5) {
        float2 fa, fb;
        fetch_f<5 + I>(va, vb, fa, fb);
        float2 f = ((lane >> I) & 1) ? fb : fa;
        float2 nxt = (I == 0) ? f : cmulf(cur, f);
        return lf_step<I + 1>(va, vb, lane, nxt);
    } else {
        return cur;
    }
}

// ================= 3-qubit register circuit =================
__device__ __forceinline__ float2 cadd3(float2 a, float2 b) {
    return make_float2(a.x + b.x, a.y + b.y);
}
__device__ __forceinline__ void run3(float x0, float x1, float x2,
                                     const float2* __restrict__ M, float E[3]) {
    float c[3], s[3];
    __sincosf(0.5f * x0, &s[0], &c[0]);
    __sincosf(0.5f * x1, &s[1], &c[1]);
    __sincosf(0.5f * x2, &s[2], &c[2]);
    float2 a[8];
#pragma unroll
    for (int i = 0; i < 8; i++) {
        float v = ((i >> 2) & 1 ? s[0] : c[0]) *
                  ((i >> 1) & 1 ? s[1] : c[1]) *
                  ((i      ) & 1 ? s[2] : c[2]);
        a[i] = make_float2(v, 0.f);
    }
#pragma unroll
    for (int l = 0; l < 4; l++) {
#pragma unroll
        for (int w = 0; w < 3; w++) {
            const float2* m = M + (l * 3 + w) * 4;
            const int p = 2 - w;
#pragma unroll
            for (int i0 = 0; i0 < 8; i0++) {
                if (i0 & (1 << p)) continue;
                int i1 = i0 | (1 << p);
                float2 A = a[i0], B = a[i1];
                a[i0] = cadd3(cmulf(m[0], A), cmulf(m[1], B));
                a[i1] = cadd3(cmulf(m[2], A), cmulf(m[3], B));
            }
        }
        const int r = (l & 1) + 1;
#pragma unroll
        for (int i = 0; i < 3; i++) {
            int pc = 2 - i;
            int pt = 2 - ((i + r) % 3);
#pragma unroll
            for (int idx = 0; idx < 8; idx++) {
                if (((idx >> pc) & 1) && !((idx >> pt) & 1)) {
                    int j = idx | (1 << pt);
                    float2 t = a[idx]; a[idx] = a[j]; a[j] = t;
                }
            }
        }
    }
    E[0] = E[1] = E[2] = 0.f;
#pragma unroll
    for (int i = 0; i < 8; i++) {
        float p = a[i].x * a[i].x + a[i].y * a[i].y;
        E[0] += (i & 4) ? -p : p;
        E[1] += (i & 2) ? -p : p;
        E[2] += (i & 1) ? -p : p;
    }
}

// ================= prep: Rot matrices =================
__global__ void prep_kernel(const float* __restrict__ t_stem,
                            const float* __restrict__ t_attn,
                            const float* __restrict__ t_ffn,
                            const float* __restrict__ t_red) {
    int i = blockIdx.x * blockDim.x + threadIdx.x;
    if (i < 960) {
        const float* a;
        if (i < 120)      a = t_stem + i * 3;
        else if (i < 600) a = t_attn + (i - 120) * 3;
        else if (i < 840) a = t_ffn  + (i - 600) * 3;
        else              a = t_red  + (i - 840) * 3;
        float phi = a[0], th = a[1], om = a[2];
        float c, s, cp, sp, cm, sm;
        sincosf(0.5f * th, &s, &c);
        sincosf(0.5f * (phi + om), &sp, &cp);
        sincosf(0.5f * (phi - om), &sm, &cm);
        float2* m = &g_mats[i * 4];
        m[0] = make_float2( cp * c, -sp * c);
        m[1] = make_float2(-cm * s, -sm * s);
        m[2] = make_float2( cm * s, -sm * s);
        m[3] = make_float2( cp * c,  sp * c);
    }
}

// ================= stem =================
__global__ void stem_kernel(const float* __restrict__ x) {
    int i = blockIdx.x * blockDim.x + threadIdx.x;
    int t = i >> 10, b = i & 1023;
    float E[3];
    run3(x[b * 30 + 3 * t], x[b * 30 + 3 * t + 1], x[b * 30 + 3 * t + 2],
         g_mats + (t * 12) * 4, E);
#pragma unroll
    for (int k = 0; k < 3; k++) g_H[b * 30 + 3 * t + k] = E[k];
}

// ================= attention: warp-resident 10-qubit simulator =================
__global__ void __launch_bounds__(128, 6) attn_kernel(int lay) {
    const int wid  = blockIdx.x * 4 + (threadIdx.x >> 5);
    const int lane = threadIdx.x & 31;
    const int b  = wid & 1023;
    const int hg = wid >> 10;
    const int h  = hg / 3, g = hg % 3;
    const float2* gm = g_mats + (120 + ((lay * 2 + h) * 3 + g) * 40) * 4;

    // ---- per-qubit factor V_q|0>, V_q = Rot(layer0,q) * RY(x_q) ----
    float2 va, vb;
    {
        int q = (lane < NT) ? lane : 0;
        float ang = (lane < NT) ? g_H[b * 30 + 3 * lane + g] : 0.f;
        float c, s;
        __sincosf(0.5f * ang, &s, &c);
        float2 g00 = gm[q * 4 + 0];
        float2 g01 = gm[q * 4 + 1];
        va = make_float2( g00.x * c + g01.x * s,  g00.y * c + g01.y * s);
        vb = make_float2(-g01.x * c + g00.x * s,  g01.y * c - g00.y * s);
    }

    // lane factor (positions 5..9), factors fetched on demand
    float2 lf = lf_step<0>(va, vb, lane, make_float2(1.f, 0.f));

    // doubling over positions 0..3 into T[16], drain position 4 into st
    u64 st[32];
    {
        float2 T[16];
        {
            float2 fa, fb; fetch_f<0>(va, vb, fa, fb);
            T[0] = cmulf(lf, fa);
            T[1] = cmulf(lf, fb);
        }
#pragma unroll
        for (int k = 1; k < 4; k++) {
            float2 fa, fb;
            if (k == 1) fetch_f<1>(va, vb, fa, fb);
            else if (k == 2) fetch_f<2>(va, vb, fa, fb);
            else fetch_f<3>(va, vb, fa, fb);
#pragma unroll
            for (int j = 0; j < 8; j++) {
                if (j < (1 << k)) {
                    T[j | (1 << k)] = cmulf(T[j], fb);
                    T[j]            = cmulf(T[j], fa);
                }
            }
        }
        {
            float2 fa, fb; fetch_f<4>(va, vb, fa, fb);
#pragma unroll
            for (int j = 0; j < 16; j++) {
                float2 hi = cmulf(T[j], fb);
                float2 lo = cmulf(T[j], fa);
                st[j]      = pack2(lo.x, lo.y);
                st[j | 16] = pack2(hi.x, hi.y);
            }
        }
    }

    // ---- layers 1..3 (conjugated gates, compile-time masks) ----
    run_gates<0>(st, gm, lane);

    // ---- measurement: incremental parity sums ----
    float res[NT];
#pragma unroll
    for (int w = 0; w < NT; w++) res[w] = 0.f;
    meas_loop<0>(st, res);
    lane_sign<0>(res, lane);
#pragma unroll
    for (int w = 0; w < NT; w++) {
#pragma unroll
        for (int off = 16; off; off >>= 1)
            res[w] += __shfl_xor_sync(0xffffffffu, res[w], off);
    }
    if (lane == 0) {
#pragma unroll
        for (int w = 0; w < NT; w++)
            g_attn[b * 60 + h * 30 + 3 * w + g] = res[w];
    }
}

// ================= fused W_O projection + residual + FFN (layer 0) ==========
__global__ void wo_ffn_kernel(const float* __restrict__ W_O, int lay) {
    int gt = blockIdx.x * blockDim.x + threadIdx.x;
    int b = gt >> 5, lane = gt & 31;

    float newH = 0.f;
    if (lane < 30) {
        const float4* wrow = (const float4*)(W_O + (lay * 30 + lane) * 60);
        const float4* arow = (const float4*)(g_attn + b * 60);
        float s0 = 0.f, s1 = 0.f, s2 = 0.f, s3 = 0.f;
#pragma unroll
        for (int k = 0; k < 15; k++) {
            float4 w4 = wrow[k];
            float4 a4 = arow[k];
            s0 = fmaf(a4.x, w4.x, s0);
            s1 = fmaf(a4.y, w4.y, s1);
            s2 = fmaf(a4.z, w4.z, s2);
            s3 = fmaf(a4.w, w4.w, s3);
        }
        newH = g_H[b * 30 + lane] + ((s0 + s1) + (s2 + s3));
    }
    __syncwarp();

    int f0 = 3 * lane, f1 = f0 + 1, f2 = f0 + 2;
    float in0 = __shfl_sync(0xffffffffu, newH, (3 * (f0 % 10) + f0 / 10) & 31);
    float in1 = __shfl_sync(0xffffffffu, newH, (3 * (f1 % 10) + f1 / 10) & 31);
    float in2 = __shfl_sync(0xffffffffu, newH, (3 * (f2 % 10) + f2 / 10) & 31);
    if (lane >= 10) { in0 = 0.f; in1 = 0.f; in2 = 0.f; }
    int t = (lane < 10) ? lane : 0;
    float E[3];
    run3(in0, in1, in2, g_mats + (600 + (lay * 10 + t) * 12) * 4, E);

    float h0 = __shfl_sync(0xffffffffu, newH, (3 * lane) & 31);
    float h1 = __shfl_sync(0xffffffffu, newH, (3 * lane + 1) & 31);
    float h2 = __shfl_sync(0xffffffffu, newH, (3 * lane + 2) & 31);
    if (lane < 10) {
        g_H[b * 30 + 3 * lane + 0] = h0 + E[0];
        g_H[b * 30 + 3 * lane + 1] = h1 + E[1];
        g_H[b * 30 + 3 * lane + 2] = h2 + E[2];
    }
}

// ===== layer-1 W_O + residual + FFN + reduce + classification, fully fused ====
__global__ void wo_ffn_cls_kernel(const float* __restrict__ W_O,
                                  const float* __restrict__ Wc,
                                  const float* __restrict__ bc,
                                  float* __restrict__ out) {
    int gt = blockIdx.x * blockDim.x + threadIdx.x;
    int b = gt >> 5, lane = gt & 31;
    const int lay = 1;

    float newH = 0.f;
    if (lane < 30) {
        const float4* wrow = (const float4*)(W_O + (lay * 30 + lane) * 60);
        const float4* arow = (const float4*)(g_attn + b * 60);
        float s0 = 0.f, s1 = 0.f, s2 = 0.f, s3 = 0.f;
#pragma unroll
        for (int k = 0; k < 15; k++) {
            float4 w4 = wrow[k];
            float4 a4 = arow[k];
            s0 = fmaf(a4.x, w4.x, s0);
            s1 = fmaf(a4.y, w4.y, s1);
            s2 = fmaf(a4.z, w4.z, s2);
            s3 = fmaf(a4.w, w4.w, s3);
        }
        newH = g_H[b * 30 + lane] + ((s0 + s1) + (s2 + s3));
    }
    __syncwarp();

    int f0 = 3 * lane, f1 = f0 + 1, f2 = f0 + 2;
    float in0 = __shfl_sync(0xffffffffu, newH, (3 * (f0 % 10) + f0 / 10) & 31);
    float in1 = __shfl_sync(0xffffffffu, newH, (3 * (f1 % 10) + f1 / 10) & 31);
    float in2 = __shfl_sync(0xffffffffu, newH, (3 * (f2 % 10) + f2 / 10) & 31);
    if (lane >= 10) { in0 = 0.f; in1 = 0.f; in2 = 0.f; }
    int t = (lane < 10) ? lane : 0;
    float E[3];
    run3(in0, in1, in2, g_mats + (600 + (lay * 10 + t) * 12) * 4, E);

    float h0 = __shfl_sync(0xffffffffu, newH, (3 * lane) & 31);
    float h1 = __shfl_sync(0xffffffffu, newH, (3 * lane + 1) & 31);
    float h2 = __shfl_sync(0xffffffffu, newH, (3 * lane + 2) & 31);

    // reduce circuit directly on register-resident H (token t = lane)
    float red = 0.f;
    {
        float hv0 = h0 + E[0], hv1 = h1 + E[1], hv2 = h2 + E[2];
        float R[3];
        run3(hv0, hv1, hv2, g_mats + (840 + t * 12) * 4, R);
        if (lane < 10) red = R[0];
    }
    float rv[10];
#pragma unroll
    for (int tt = 0; tt < 10; tt++)
        rv[tt] = __shfl_sync(0xffffffffu, red, tt);
    if (lane < 10) {
        float s = bc[lane];
#pragma unroll
        for (int tt = 0; tt < 10; tt++) s = fmaf(rv[tt], Wc[lane * 10 + tt], s);
        out[b * 10 + lane] = s;
    }
}

// ================= launch =================
extern "C" void kernel_launch(void* const* d_in, const int* in_sizes, int n_in,
                              void* d_out, int out_size) {
    const float* x_      = (const float*)d_in[0];
    const float* t_stem  = (const float*)d_in[1];
    const float* t_attn  = (const float*)d_in[2];
    const float* W_O     = (const float*)d_in[3];
    const float* t_ffn   = (const float*)d_in[4];
    const float* t_red   = (const float*)d_in[5];
    const float* W_cls   = (const float*)d_in[6];
    const float* b_cls   = (const float*)d_in[7];
    float* out = (float*)d_out;

    prep_kernel<<<4, 256>>>(t_stem, t_attn, t_ffn, t_red);
    stem_kernel<<<40, 256>>>(x_);
    attn_kernel<<<1536, 128>>>(0);
    wo_ffn_kernel<<<128, 256>>>(W_O, 0);
    attn_kernel<<<1536, 128>>>(1);
    wo_ffn_cls_kernel<<<128, 256>>>(W_O, W_cls, b_cls, out);
}

// round 8
// speedup vs baseline: 1.2831x; 1.1130x over previous
#include <cuda_runtime.h>
#include <math.h>

#define BATCH   1024
#define NT      10
#define PADDED  30
#define DEPTH   4
#define LAYERS  2
#define NHEADS  2
#define NCLS    10

typedef unsigned long long u64;

// g_mats layout (each matrix = 4 float2, row-major 2x2):
//   stem   : [0,120)    (t*4+l)*3+w
//   attn   : [120,600)  (((lay*2+h)*3+g)*4+l)*10+w
//   ffn    : [600,840)  ((lay*10+t)*4+l)*3+w
//   reduce : [840,960)  (t*4+l)*3+w
__device__ float2 g_mats[960 * 4];
__device__ float  g_H[BATCH * PADDED];
__device__ float  g_attn[BATCH * PADDED * NHEADS];

// ================= compile-time GF(2) mask tables =================
__host__ __device__ constexpr int parity(unsigned x) {
    int p = 0; while (x) { p ^= (int)(x & 1u); x >>= 1; } return p;
}

struct Masks {
    unsigned pm[DEPTH][NT];
    unsigned am[DEPTH][NT];
    unsigned zm[NT];
};

__host__ __device__ constexpr Masks make_masks() {
    Masks M{};
    for (int l = 0; l < DEPTH; l++) {
        unsigned R[NT]{}, Ri[NT]{};
        for (int u = 0; u < NT; u++) { R[u] = 1u << u; Ri[u] = 1u << u; }
        for (int ll = 0; ll < l; ll++) {
            int r = ll + 1;
            for (int i = 0; i < NT; i++) R[(i + r) % NT] ^= R[i];
        }
        for (int ll = l - 1; ll >= 0; ll--) {
            int r = ll + 1;
            for (int i = NT - 1; i >= 0; i--) Ri[(i + r) % NT] ^= Ri[i];
        }
        for (int w = 0; w < NT; w++) {
            unsigned m = 0;
            for (int u = 0; u < NT; u++) if ((Ri[u] >> w) & 1u) m |= 1u << u;
            M.pm[l][w] = m;
            M.am[l][w] = R[w];
        }
    }
    unsigned R[NT]{};
    for (int u = 0; u < NT; u++) R[u] = 1u << u;
    for (int ll = 0; ll < DEPTH; ll++) {
        int r = ll + 1;
        for (int i = 0; i < NT; i++) R[(i + r) % NT] ^= R[i];
    }
    for (int w = 0; w < NT; w++) M.zm[w] = R[w];
    return M;
}

struct Masks2 {
    unsigned pm[3][NT];
    unsigned am[3][NT];
    unsigned zm[NT];
    int posq[NT];
};

__host__ __device__ constexpr Masks2 make_masks2() {
    Masks M = make_masks();
    unsigned bestS = 0x1Fu; int bestScore = -1;
    for (unsigned S = 0; S < 1024u; S++) {
        int pc = 0;
        for (int q = 0; q < NT; q++) pc += (int)((S >> q) & 1u);
        if (pc != 5) continue;
        int score = 0;
        for (int l = 1; l < DEPTH; l++)
            for (int w = 0; w < NT; w++)
                if ((M.pm[l][w] & ~S & 0x3FFu) == 0u) score++;
        if (score > bestScore) { bestScore = score; bestS = S; }
    }
    int qpos[NT]{};
    Masks2 R{};
    {
        int lp = 0, hp = 5;
        for (int q = 0; q < NT; q++) {
            int p = ((bestS >> q) & 1u) ? lp++ : hp++;
            qpos[q] = p;
        }
        for (int q = 0; q < NT; q++) R.posq[qpos[q]] = q;
    }
    for (int l = 1; l < DEPTH; l++)
        for (int w = 0; w < NT; w++) {
            unsigned pm2 = 0, am2 = 0;
            for (int q = 0; q < NT; q++) {
                if ((M.pm[l][w] >> q) & 1u) pm2 |= 1u << qpos[q];
                if ((M.am[l][w] >> q) & 1u) am2 |= 1u << qpos[q];
            }
            R.pm[l - 1][w] = pm2;
            R.am[l - 1][w] = am2;
        }
    for (int w = 0; w < NT; w++) {
        unsigned z2 = 0;
        for (int q = 0; q < NT; q++) if ((M.zm[w] >> q) & 1u) z2 |= 1u << qpos[q];
        R.zm[w] = z2;
    }
    return R;
}
constexpr Masks2 MK2 = make_masks2();

// ================= packed f32x2 complex helpers =================
__device__ __forceinline__ u64 pack2(float lo, float hi) {
    u64 r; asm("mov.b64 %0, {%1,%2};" : "=l"(r) : "f"(lo), "f"(hi)); return r;
}
__device__ __forceinline__ float2 unpack2(u64 a) {
    float2 f; asm("mov.b64 {%0,%1}, %2;" : "=f"(f.x), "=f"(f.y) : "l"(a)); return f;
}
__device__ __forceinline__ u64 swap2(u64 a) {
    u64 r; asm("{ .reg .b32 lo, hi; mov.b64 {lo,hi}, %1; mov.b64 %0, {hi,lo}; }" : "=l"(r) : "l"(a)); return r;
}
__device__ __forceinline__ u64 f2fma(u64 a, u64 b, u64 c) {
    u64 r; asm("fma.rn.f32x2 %0, %1, %2, %3;" : "=l"(r) : "l"(a), "l"(b), "l"(c)); return r;
}
__device__ __forceinline__ u64 f2mul(u64 a, u64 b) {
    u64 r; asm("mul.rn.f32x2 %0, %1, %2;" : "=l"(r) : "l"(a), "l"(b)); return r;
}
__device__ __forceinline__ u64 shfl64_xor(u64 v, int m) {
    unsigned lo = (unsigned)v, hi = (unsigned)(v >> 32);
    lo = __shfl_xor_sync(0xffffffffu, lo, m);
    hi = __shfl_xor_sync(0xffffffffu, hi, m);
    return ((u64)hi << 32) | lo;
}

__device__ __forceinline__ u64 cmix(u64 A, u64 As, u64 B, u64 Bs,
                                    u64 oxx, u64 oyy, u64 txx, u64 tyy) {
    return f2fma(oxx, A, f2fma(oyy, As, f2fma(txx, B, f2mul(tyy, Bs))));
}

__device__ __forceinline__ float2 cmulf(float2 a, float2 b) {
    return make_float2(a.x * b.x - a.y * b.y, a.x * b.y + a.y * b.x);
}

// ================= gate application (all indices compile-time) =================
template<unsigned MLO, unsigned ALO, int J>
__device__ __forceinline__ void local_loop(u64* st, u64 oxx, u64 tyy,
                                           u64 oyy0, u64 oyy1, u64 txx0, u64 txx1) {
    if constexpr (J < 32) {
        constexpr unsigned LOW = MLO & (0u - MLO);
        if constexpr ((J & (int)LOW) == 0) {
            constexpr int J2 = J ^ (int)MLO;
            constexpr int P  = parity(ALO & (unsigned)J);
            constexpr int P2 = parity(ALO & (unsigned)J2);
            u64 A = st[J], B = st[J2];
            u64 As = swap2(A), Bs = swap2(B);
            st[J]  = cmix(A, As, B, Bs, oxx, P  ? oyy1 : oyy0, P  ? txx1 : txx0, tyy);
            st[J2] = cmix(B, Bs, A, As, oxx, P2 ? oyy1 : oyy0, P2 ? txx1 : txx0, tyy);
        }
        local_loop<MLO, ALO, J + 1>(st, oxx, tyy, oyy0, oyy1, txx0, txx1);
    }
}

template<unsigned MHI, unsigned ALO, int J>
__device__ __forceinline__ void lane_loop(u64* st, u64 oxx, u64 tyy,
                                          u64 oyy0, u64 oyy1, u64 txx0, u64 txx1) {
    if constexpr (J < 32) {
        constexpr int P = parity(ALO & (unsigned)J);
        u64 A = st[J];
        u64 B = shfl64_xor(A, (int)MHI);
        u64 As = swap2(A), Bs = swap2(B);
        st[J] = cmix(A, As, B, Bs, oxx, P ? oyy1 : oyy0, P ? txx1 : txx0, tyy);
        lane_loop<MHI, ALO, J + 1>(st, oxx, tyy, oyy0, oyy1, txx0, txx1);
    }
}

template<unsigned MLO, unsigned MHI, unsigned ALO, int J>
__device__ __forceinline__ void mixed_loop(u64* st, u64 oxx, u64 tyy,
                                           u64 oyy0, u64 oyy1, u64 txx0, u64 txx1) {
    if constexpr (J < 32) {
        constexpr unsigned LOW = MLO & (0u - MLO);
        if constexpr ((J & (int)LOW) == 0) {
            constexpr int J2 = J ^ (int)MLO;
            constexpr int P  = parity(ALO & (unsigned)J);
            constexpr int P2 = parity(ALO & (unsigned)J2);
            u64 A = st[J], B = st[J2];
            u64 pA = shfl64_xor(B, (int)MHI);
            u64 pB = shfl64_xor(A, (int)MHI);
            u64 As = swap2(A), Bs = swap2(B), pAs = swap2(pA), pBs = swap2(pB);
            st[J]  = cmix(A, As, pA, pAs, oxx, P  ? oyy1 : oyy0, P  ? txx1 : txx0, tyy);
            st[J2] = cmix(B, Bs, pB, pBs, oxx, P2 ? oyy1 : oyy0, P2 ? txx1 : txx0, tyy);
        }
        mixed_loop<MLO, MHI, ALO, J + 1>(st, oxx, tyy, oyy0, oyy1, txx0, txx1);
    }
}

template<int L, int W>
__device__ __forceinline__ void apply_gate(u64* st, const float2* __restrict__ gm, int lane) {
    constexpr unsigned m   = MK2.pm[L][W];
    constexpr unsigned a   = MK2.am[L][W];
    constexpr unsigned mlo = m & 31u, mhi = (m >> 5) & 31u;
    constexpr unsigned alo = a & 31u, ahi = (a >> 5) & 31u;
    float2 g00 = gm[((L + 1) * 10 + W) * 4 + 0];
    float2 g01 = gm[((L + 1) * 10 + W) * 4 + 1];
    u64 oxx = pack2(g00.x, g00.x);
    u64 oyy = pack2(-g00.y, g00.y);
    u64 txx = pack2(g01.x, g01.x);
    u64 tyy = pack2(-g01.y, g01.y);
    constexpr u64 SGN = 0x8000000080000000ull;
    u64 oyyN = oyy ^ SGN;
    u64 txxN = txx ^ SGN;
    int plane = (int)(__popc(ahi & (unsigned)lane) & 1);
    u64 oyy0 = plane ? oyyN : oyy;
    u64 oyy1 = plane ? oyy  : oyyN;
    u64 txx0 = plane ? txxN : txx;
    u64 txx1 = plane ? txx  : txxN;
    if constexpr (mhi == 0u) {
        local_loop<mlo, alo, 0>(st, oxx, tyy, oyy0, oyy1, txx0, txx1);
    } else if constexpr (mlo == 0u) {
        lane_loop<mhi, alo, 0>(st, oxx, tyy, oyy0, oyy1, txx0, txx1);
    } else {
        mixed_loop<mlo, mhi, alo, 0>(st, oxx, tyy, oyy0, oyy1, txx0, txx1);
    }
}

template<int G>
__device__ __forceinline__ void run_gates(u64* st, const float2* __restrict__ gm, int lane) {
    if constexpr (G < 3 * NT) {
        apply_gate<G / NT, G % NT>(st, gm, lane);
        run_gates<G + 1>(st, gm, lane);
    }
}

// ================= measurement: in-place FWHT over local bits =================
template<int K, int J>
__device__ __forceinline__ void fwht_stage(float* pr) {
    if constexpr (J < 32) {
        if constexpr ((J & (1 << K)) == 0) {
            constexpr int J2 = J | (1 << K);
            float a = pr[J], b = pr[J2];
            pr[J]  = a + b;
            pr[J2] = a - b;
        }
        fwht_stage<K, J + 1>(pr);
    }
}
template<int K>
__device__ __forceinline__ void fwht(float* pr) {
    if constexpr (K < 5) {
        fwht_stage<K, 0>(pr);
        fwht<K + 1>(pr);
    }
}
// res[w] = pr_fwht[zlo_w], with lane-bit parity sign
template<int W>
__device__ __forceinline__ void meas_from(const float* pr, float* res, int lane) {
    if constexpr (W < NT) {
        constexpr unsigned z = MK2.zm[W];
        constexpr unsigned zlo = z & 31u, zhi = (z >> 5) & 31u;
        float acc = pr[zlo];
        int sl = (int)(__popc(zhi & (unsigned)lane) & 1);
        res[W] = sl ? -acc : acc;
        meas_from<W + 1>(pr, res, lane);
    }
}

// compile-time posq gather of embedding factors into position order
template<int P>
__device__ __forceinline__ void gather_factors(float2* fa, float2* fb, float2 va, float2 vb) {
    if constexpr (P < NT) {
        constexpr int q = MK2.posq[P];
        fa[P].x = __shfl_sync(0xffffffffu, va.x, q);
        fa[P].y = __shfl_sync(0xffffffffu, va.y, q);
        fb[P].x = __shfl_sync(0xffffffffu, vb.x, q);
        fb[P].y = __shfl_sync(0xffffffffu, vb.y, q);
        gather_factors<P + 1>(fa, fb, va, vb);
    }
}

// ================= 3-qubit register circuit =================
__device__ __forceinline__ float2 cadd3(float2 a, float2 b) {
    return make_float2(a.x + b.x, a.y + b.y);
}
__device__ __forceinline__ void run3(float x0, float x1, float x2,
                                     const float2* __restrict__ M, float E[3]) {
    float c[3], s[3];
    __sincosf(0.5f * x0, &s[0], &c[0]);
    __sincosf(0.5f * x1, &s[1], &c[1]);
    __sincosf(0.5f * x2, &s[2], &c[2]);
    float2 a[8];
#pragma unroll
    for (int i = 0; i < 8; i++) {
        float v = ((i >> 2) & 1 ? s[0] : c[0]) *
                  ((i >> 1) & 1 ? s[1] : c[1]) *
                  ((i      ) & 1 ? s[2] : c[2]);
        a[i] = make_float2(v, 0.f);
    }
#pragma unroll
    for (int l = 0; l < 4; l++) {
#pragma unroll
        for (int w = 0; w < 3; w++) {
            const float2* m = M + (l * 3 + w) * 4;
            const int p = 2 - w;
#pragma unroll
            for (int i0 = 0; i0 < 8; i0++) {
                if (i0 & (1 << p)) continue;
                int i1 = i0 | (1 << p);
                float2 A = a[i0], B = a[i1];
                a[i0] = cadd3(cmulf(m[0], A), cmulf(m[1], B));
                a[i1] = cadd3(cmulf(m[2], A), cmulf(m[3], B));
            }
        }
        const int r = (l & 1) + 1;
#pragma unroll
        for (int i = 0; i < 3; i++) {
            int pc = 2 - i;
            int pt = 2 - ((i + r) % 3);
#pragma unroll
            for (int idx = 0; idx < 8; idx++) {
                if (((idx >> pc) & 1) && !((idx >> pt) & 1)) {
                    int j = idx | (1 << pt);
                    float2 t = a[idx]; a[idx] = a[j]; a[j] = t;
                }
            }
        }
    }
    E[0] = E[1] = E[2] = 0.f;
#pragma unroll
    for (int i = 0; i < 8; i++) {
        float p = a[i].x * a[i].x + a[i].y * a[i].y;
        E[0] += (i & 4) ? -p : p;
        E[1] += (i & 2) ? -p : p;
        E[2] += (i & 1) ? -p : p;
    }
}

// ================= prep: Rot matrices =================
__global__ void prep_kernel(const float* __restrict__ t_stem,
                            const float* __restrict__ t_attn,
                            const float* __restrict__ t_ffn,
                            const float* __restrict__ t_red) {
    int i = blockIdx.x * blockDim.x + threadIdx.x;
    if (i < 960) {
        const float* a;
        if (i < 120)      a = t_stem + i * 3;
        else if (i < 600) a = t_attn + (i - 120) * 3;
        else if (i < 840) a = t_ffn  + (i - 600) * 3;
        else              a = t_red  + (i - 840) * 3;
        float phi = a[0], th = a[1], om = a[2];
        float c, s, cp, sp, cm, sm;
        sincosf(0.5f * th, &s, &c);
        sincosf(0.5f * (phi + om), &sp, &cp);
        sincosf(0.5f * (phi - om), &sm, &cm);
        float2* m = &g_mats[i * 4];
        m[0] = make_float2( cp * c, -sp * c);
        m[1] = make_float2(-cm * s, -sm * s);
        m[2] = make_float2( cm * s, -sm * s);
        m[3] = make_float2( cp * c,  sp * c);
    }
}

// ================= stem =================
__global__ void stem_kernel(const float* __restrict__ x) {
    int i = blockIdx.x * blockDim.x + threadIdx.x;
    int t = i >> 10, b = i & 1023;
    float E[3];
    run3(x[b * 30 + 3 * t], x[b * 30 + 3 * t + 1], x[b * 30 + 3 * t + 2],
         g_mats + (t * 12) * 4, E);
#pragma unroll
    for (int k = 0; k < 3; k++) g_H[b * 30 + 3 * t + k] = E[k];
}

// ================= attention: warp-resident 10-qubit simulator (R5 body) ======
__global__ void __launch_bounds__(128) attn_kernel(int lay) {
    const int wid  = blockIdx.x * 4 + (threadIdx.x >> 5);
    const int lane = threadIdx.x & 31;
    const int b  = wid & 1023;
    const int hg = wid >> 10;
    const int h  = hg / 3, g = hg % 3;
    const float2* gm = g_mats + (120 + ((lay * 2 + h) * 3 + g) * 40) * 4;

    // ---- init: product state of V_q|0>, V_q = Rot(layer0,q) * RY(x_q) ----
    float2 va, vb;
    {
        int q = (lane < NT) ? lane : 0;
        float ang = (lane < NT) ? g_H[b * 30 + 3 * lane + g] : 0.f;
        float c, s;
        __sincosf(0.5f * ang, &s, &c);
        float2 g00 = gm[q * 4 + 0];
        float2 g01 = gm[q * 4 + 1];
        va = make_float2( g00.x * c + g01.x * s,  g00.y * c + g01.y * s);
        vb = make_float2(-g01.x * c + g00.x * s,  g01.y * c - g00.y * s);
    }
    float2 fa[NT], fb[NT];
    gather_factors<0>(fa, fb, va, vb);
    float2 lf = (lane & 1) ? fb[5] : fa[5];
#pragma unroll
    for (int p = 6; p < NT; p++)
        lf = cmulf(lf, ((lane >> (p - 5)) & 1) ? fb[p] : fa[p]);
    float2 T[32];
    T[0] = cmulf(lf, fa[0]);
    T[1] = cmulf(lf, fb[0]);
#pragma unroll
    for (int k = 1; k < 5; k++) {
#pragma unroll
        for (int j = 0; j < 16; j++) {
            if (j < (1 << k)) {
                T[j | (1 << k)] = cmulf(T[j], fb[k]);
                T[j]            = cmulf(T[j], fa[k]);
            }
        }
    }
    u64 st[32];
#pragma unroll
    for (int j = 0; j < 32; j++) st[j] = pack2(T[j].x, T[j].y);

    // ---- layers 1..3 (conjugated gates, compile-time masks) ----
    run_gates<0>(st, gm, lane);

    // ---- measurement: |amp|^2, FWHT, pick masks ----
    float pr[32];
#pragma unroll
    for (int j = 0; j < 32; j++) {
        float2 f = unpack2(st[j]);
        pr[j] = f.x * f.x + f.y * f.y;
    }
    fwht<0>(pr);
    float res[NT];
    meas_from<0>(pr, res, lane);
#pragma unroll
    for (int w = 0; w < NT; w++) {
#pragma unroll
        for (int off = 16; off; off >>= 1)
            res[w] += __shfl_xor_sync(0xffffffffu, res[w], off);
    }
    if (lane == 0) {
#pragma unroll
        for (int w = 0; w < NT; w++)
            g_attn[b * 60 + h * 30 + 3 * w + g] = res[w];
    }
}

// ================= fused W_O projection + residual + FFN (layer 0) ==========
__global__ void wo_ffn_kernel(const float* __restrict__ W_O, int lay) {
    int gt = blockIdx.x * blockDim.x + threadIdx.x;
    int b = gt >> 5, lane = gt & 31;

    float newH = 0.f;
    if (lane < 30) {
        const float4* wrow = (const float4*)(W_O + (lay * 30 + lane) * 60);
        const float4* arow = (const float4*)(g_attn + b * 60);
        float s0 = 0.f, s1 = 0.f, s2 = 0.f, s3 = 0.f;
#pragma unroll
        for (int k = 0; k < 15; k++) {
            float4 w4 = wrow[k];
            float4 a4 = arow[k];
            s0 = fmaf(a4.x, w4.x, s0);
            s1 = fmaf(a4.y, w4.y, s1);
            s2 = fmaf(a4.z, w4.z, s2);
            s3 = fmaf(a4.w, w4.w, s3);
        }
        newH = g_H[b * 30 + lane] + ((s0 + s1) + (s2 + s3));
    }
    __syncwarp();

    int f0 = 3 * lane, f1 = f0 + 1, f2 = f0 + 2;
    float in0 = __shfl_sync(0xffffffffu, newH, (3 * (f0 % 10) + f0 / 10) & 31);
    float in1 = __shfl_sync(0xffffffffu, newH, (3 * (f1 % 10) + f1 / 10) & 31);
    float in2 = __shfl_sync(0xffffffffu, newH, (3 * (f2 % 10) + f2 / 10) & 31);
    if (lane >= 10) { in0 = 0.f; in1 = 0.f; in2 = 0.f; }
    int t = (lane < 10) ? lane : 0;
    float E[3];
    run3(in0, in1, in2, g_mats + (600 + (lay * 10 + t) * 12) * 4, E);

    float h0 = __shfl_sync(0xffffffffu, newH, (3 * lane) & 31);
    float h1 = __shfl_sync(0xffffffffu, newH, (3 * lane + 1) & 31);
    float h2 = __shfl_sync(0xffffffffu, newH, (3 * lane + 2) & 31);
    if (lane < 10) {
        g_H[b * 30 + 3 * lane + 0] = h0 + E[0];
        g_H[b * 30 + 3 * lane + 1] = h1 + E[1];
        g_H[b * 30 + 3 * lane + 2] = h2 + E[2];
    }
}

// ===== layer-1 W_O + residual + FFN + reduce + classification, fully fused ====
__global__ void wo_ffn_cls_kernel(const float* __restrict__ W_O,
                                  const float* __restrict__ Wc,
                                  const float* __restrict__ bc,
                                  float* __restrict__ out) {
    int gt = blockIdx.x * blockDim.x + threadIdx.x;
    int b = gt >> 5, lane = gt & 31;
    const int lay = 1;

    float newH = 0.f;
    if (lane < 30) {
        const float4* wrow = (const float4*)(W_O + (lay * 30 + lane) * 60);
        const float4* arow = (const float4*)(g_attn + b * 60);
        float s0 = 0.f, s1 = 0.f, s2 = 0.f, s3 = 0.f;
#pragma unroll
        for (int k = 0; k < 15; k++) {
            float4 w4 = wrow[k];
            float4 a4 = arow[k];
            s0 = fmaf(a4.x, w4.x, s0);
            s1 = fmaf(a4.y, w4.y, s1);
            s2 = fmaf(a4.z, w4.z, s2);
            s3 = fmaf(a4.w, w4.w, s3);
        }
        newH = g_H[b * 30 + lane] + ((s0 + s1) + (s2 + s3));
    }
    __syncwarp();

    int f0 = 3 * lane, f1 = f0 + 1, f2 = f0 + 2;
    float in0 = __shfl_sync(0xffffffffu, newH, (3 * (f0 % 10) + f0 / 10) & 31);
    float in1 = __shfl_sync(0xffffffffu, newH, (3 * (f1 % 10) + f1 / 10) & 31);
    float in2 = __shfl_sync(0xffffffffu, newH, (3 * (f2 % 10) + f2 / 10) & 31);
    if (lane >= 10) { in0 = 0.f; in1 = 0.f; in2 = 0.f; }
    int t = (lane < 10) ? lane : 0;
    float E[3];
    run3(in0, in1, in2, g_mats + (600 + (lay * 10 + t) * 12) * 4, E);

    float h0 = __shfl_sync(0xffffffffu, newH, (3 * lane) & 31);
    float h1 = __shfl_sync(0xffffffffu, newH, (3 * lane + 1) & 31);
    float h2 = __shfl_sync(0xffffffffu, newH, (3 * lane + 2) & 31);

    // reduce circuit directly on register-resident H (token t = lane)
    float red = 0.f;
    {
        float hv0 = h0 + E[0], hv1 = h1 + E[1], hv2 = h2 + E[2];
        float R[3];
        run3(hv0, hv1, hv2, g_mats + (840 + t * 12) * 4, R);
        if (lane < 10) red = R[0];
    }
    float rv[10];
#pragma unroll
    for (int tt = 0; tt < 10; tt++)
        rv[tt] = __shfl_sync(0xffffffffu, red, tt);
    if (lane < 10) {
        float s = bc[lane];
#pragma unroll
        for (int tt = 0; tt < 10; tt++) s = fmaf(rv[tt], Wc[lane * 10 + tt], s);
        out[b * 10 + lane] = s;
    }
}

// ================= launch =================
extern "C" void kernel_launch(void* const* d_in, const int* in_sizes, int n_in,
                              void* d_out, int out_size) {
    const float* x_      = (const float*)d_in[0];
    const float* t_stem  = (const float*)d_in[1];
    const float* t_attn  = (const float*)d_in[2];
    const float* W_O     = (const float*)d_in[3];
    const float* t_ffn   = (const float*)d_in[4];
    const float* t_red   = (const float*)d_in[5];
    const float* W_cls   = (const float*)d_in[6];
    const float* b_cls   = (const float*)d_in[7];
    float* out = (float*)d_out;

    prep_kernel<<<4, 256>>>(t_stem, t_attn, t_ffn, t_red);
    stem_kernel<<<40, 256>>>(x_);
    attn_kernel<<<1536, 128>>>(0);
    wo_ffn_kernel<<<128, 256>>>(W_O, 0);
    attn_kernel<<<1536, 128>>>(1);
    wo_ffn_cls_kernel<<<128, 256>>>(W_O, W_cls, b_cls, out);
}

// round 9
// speedup vs baseline: 1.3032x; 1.0156x over previous
#include <cuda_runtime.h>
#include <math.h>

#define BATCH   1024
#define NT      10
#define PADDED  30
#define DEPTH   4
#define LAYERS  2
#define NHEADS  2
#define NCLS    10

typedef unsigned long long u64;

// g_mats layout (each matrix = 4 float2, row-major 2x2):
//   stem   : [0,120)    (t*4+l)*3+w
//   attn   : [120,600)  (((lay*2+h)*3+g)*4+l)*10+w
//   ffn    : [600,840)  ((lay*10+t)*4+l)*3+w
//   reduce : [840,960)  (t*4+l)*3+w
__device__ float2 g_mats[960 * 4];
__device__ float  g_H[BATCH * PADDED];
__device__ float  g_attn[BATCH * PADDED * NHEADS];

// ================= compile-time GF(2) mask tables =================
__host__ __device__ constexpr int parity(unsigned x) {
    int p = 0; while (x) { p ^= (int)(x & 1u); x >>= 1; } return p;
}

struct Masks {
    unsigned pm[DEPTH][NT];
    unsigned am[DEPTH][NT];
    unsigned zm[NT];
};

__host__ __device__ constexpr Masks make_masks() {
    Masks M{};
    for (int l = 0; l < DEPTH; l++) {
        unsigned R[NT]{}, Ri[NT]{};
        for (int u = 0; u < NT; u++) { R[u] = 1u << u; Ri[u] = 1u << u; }
        for (int ll = 0; ll < l; ll++) {
            int r = ll + 1;
            for (int i = 0; i < NT; i++) R[(i + r) % NT] ^= R[i];
        }
        for (int ll = l - 1; ll >= 0; ll--) {
            int r = ll + 1;
            for (int i = NT - 1; i >= 0; i--) Ri[(i + r) % NT] ^= Ri[i];
        }
        for (int w = 0; w < NT; w++) {
            unsigned m = 0;
            for (int u = 0; u < NT; u++) if ((Ri[u] >> w) & 1u) m |= 1u << u;
            M.pm[l][w] = m;
            M.am[l][w] = R[w];
        }
    }
    unsigned R[NT]{};
    for (int u = 0; u < NT; u++) R[u] = 1u << u;
    for (int ll = 0; ll < DEPTH; ll++) {
        int r = ll + 1;
        for (int i = 0; i < NT; i++) R[(i + r) % NT] ^= R[i];
    }
    for (int w = 0; w < NT; w++) M.zm[w] = R[w];
    return M;
}

struct Masks2 {
    unsigned pm[3][NT];
    unsigned am[3][NT];
    unsigned zm[NT];
    int posq[NT];
};

__host__ __device__ constexpr Masks2 make_masks2() {
    Masks M = make_masks();
    unsigned bestS = 0x1Fu; int bestScore = -1;
    for (unsigned S = 0; S < 1024u; S++) {
        int pc = 0;
        for (int q = 0; q < NT; q++) pc += (int)((S >> q) & 1u);
        if (pc != 5) continue;
        int score = 0;
        for (int l = 1; l < DEPTH; l++)
            for (int w = 0; w < NT; w++)
                if ((M.pm[l][w] & ~S & 0x3FFu) == 0u) score++;
        if (score > bestScore) { bestScore = score; bestS = S; }
    }
    int qpos[NT]{};
    Masks2 R{};
    {
        int lp = 0, hp = 5;
        for (int q = 0; q < NT; q++) {
            int p = ((bestS >> q) & 1u) ? lp++ : hp++;
            qpos[q] = p;
        }
        for (int q = 0; q < NT; q++) R.posq[qpos[q]] = q;
    }
    for (int l = 1; l < DEPTH; l++)
        for (int w = 0; w < NT; w++) {
            unsigned pm2 = 0, am2 = 0;
            for (int q = 0; q < NT; q++) {
                if ((M.pm[l][w] >> q) & 1u) pm2 |= 1u << qpos[q];
                if ((M.am[l][w] >> q) & 1u) am2 |= 1u << qpos[q];
            }
            R.pm[l - 1][w] = pm2;
            R.am[l - 1][w] = am2;
        }
    for (int w = 0; w < NT; w++) {
        unsigned z2 = 0;
        for (int q = 0; q < NT; q++) if ((M.zm[w] >> q) & 1u) z2 |= 1u << qpos[q];
        R.zm[w] = z2;
    }
    return R;
}
constexpr Masks2 MK2 = make_masks2();

// ================= packed f32x2 helpers =================
__device__ __forceinline__ u64 pack2(float lo, float hi) {
    u64 r; asm("mov.b64 %0, {%1,%2};" : "=l"(r) : "f"(lo), "f"(hi)); return r;
}
__device__ __forceinline__ float2 unpack2(u64 a) {
    float2 f; asm("mov.b64 {%0,%1}, %2;" : "=f"(f.x), "=f"(f.y) : "l"(a)); return f;
}
__device__ __forceinline__ u64 swap2(u64 a) {
    u64 r; asm("{ .reg .b32 lo, hi; mov.b64 {lo,hi}, %1; mov.b64 %0, {hi,lo}; }" : "=l"(r) : "l"(a)); return r;
}
__device__ __forceinline__ u64 f2fma(u64 a, u64 b, u64 c) {
    u64 r; asm("fma.rn.f32x2 %0, %1, %2, %3;" : "=l"(r) : "l"(a), "l"(b), "l"(c)); return r;
}
__device__ __forceinline__ u64 f2mul(u64 a, u64 b) {
    u64 r; asm("mul.rn.f32x2 %0, %1, %2;" : "=l"(r) : "l"(a), "l"(b)); return r;
}
__device__ __forceinline__ u64 shfl64_xor(u64 v, int m) {
    unsigned lo = (unsigned)v, hi = (unsigned)(v >> 32);
    lo = __shfl_xor_sync(0xffffffffu, lo, m);
    hi = __shfl_xor_sync(0xffffffffu, hi, m);
    return ((u64)hi << 32) | lo;
}

__device__ __forceinline__ float2 cmulf(float2 a, float2 b) {
    return make_float2(a.x * b.x - a.y * b.y, a.x * b.y + a.y * b.x);
}

// ================= SoA butterfly =================
// X (parity p of lo amp), partner Y.
// out_re = cx*Xr + CYRE_p*Xi + DXRE_p*Yr + (-dy)*Yi
// out_im = cx*Xi + CYRE_{p^1}*Xr + DXRE_p*Yi + ( dy)*Yr
__device__ __forceinline__ void soa_bfly(u64 xr, u64 xi, u64 yr, u64 yi,
                                         u64 CX, u64 cyp, u64 cyq, u64 dxp,
                                         u64 DYRE, u64 DYIM, u64& nr, u64& ni) {
    nr = f2fma(CX, xr, f2fma(cyp, xi, f2fma(dxp, yr, f2mul(DYRE, yi))));
    ni = f2fma(CX, xi, f2fma(cyq, xr, f2fma(dxp, yi, f2mul(DYIM, yr))));
}

// Case A: pure local, bit4 not in pair mask
template<unsigned MLO4, unsigned ALO4, int J>
__device__ __forceinline__ void loopA(u64* re, u64* im, u64 CX, u64 cy0, u64 cy1,
                                      u64 dx0, u64 dx1, u64 DYRE, u64 DYIM) {
    if constexpr (J < 16) {
        constexpr unsigned LOW = MLO4 & (0u - MLO4);
        if constexpr ((J & (int)LOW) == 0) {
            constexpr int J2 = J ^ (int)MLO4;
            constexpr int P  = parity(ALO4 & (unsigned)J);
            constexpr int P2 = parity(ALO4 & (unsigned)J2);
            u64 ar = re[J], ai = im[J], br = re[J2], bi = im[J2];
            u64 nr1, ni1, nr2, ni2;
            soa_bfly(ar, ai, br, bi, CX, P  ? cy1 : cy0, P  ? cy0 : cy1, P  ? dx1 : dx0, DYRE, DYIM, nr1, ni1);
            soa_bfly(br, bi, ar, ai, CX, P2 ? cy1 : cy0, P2 ? cy0 : cy1, P2 ? dx1 : dx0, DYRE, DYIM, nr2, ni2);
            re[J] = nr1; im[J] = ni1; re[J2] = nr2; im[J2] = ni2;
        }
        loopA<MLO4, ALO4, J + 1>(re, im, CX, cy0, cy1, dx0, dx1, DYRE, DYIM);
    }
}

// Case B: pair mask == bit4 only (partner = other half of same reg)
template<unsigned ALO4, int J>
__device__ __forceinline__ void loopB(u64* re, u64* im, u64 CX, u64 cy0, u64 cy1,
                                      u64 dx0, u64 dx1, u64 DYRE, u64 DYIM) {
    if constexpr (J < 16) {
        constexpr int P = parity(ALO4 & (unsigned)J);
        u64 yr = swap2(re[J]), yi = swap2(im[J]);
        u64 nr, ni;
        soa_bfly(re[J], im[J], yr, yi, CX, P ? cy1 : cy0, P ? cy0 : cy1, P ? dx1 : dx0, DYRE, DYIM, nr, ni);
        re[J] = nr; im[J] = ni;
        loopB<ALO4, J + 1>(re, im, CX, cy0, cy1, dx0, dx1, DYRE, DYIM);
    }
}

// Case C: local with bit4 + low bits (partner = other reg, swapped halves)
template<unsigned MLO4, unsigned ALO4, int J>
__device__ __forceinline__ void loopC(u64* re, u64* im, u64 CX, u64 cy0, u64 cy1,
                                      u64 dx0, u64 dx1, u64 DYRE, u64 DYIM) {
    if constexpr (J < 16) {
        constexpr unsigned LOW = MLO4 & (0u - MLO4);
        if constexpr ((J & (int)LOW) == 0) {
            constexpr int J2 = J ^ (int)MLO4;
            constexpr int P  = parity(ALO4 & (unsigned)J);
            constexpr int P2 = parity(ALO4 & (unsigned)J2);
            u64 y1r = swap2(re[J2]), y1i = swap2(im[J2]);
            u64 y2r = swap2(re[J]),  y2i = swap2(im[J]);
            u64 nr1, ni1, nr2, ni2;
            soa_bfly(re[J],  im[J],  y1r, y1i, CX, P  ? cy1 : cy0, P  ? cy0 : cy1, P  ? dx1 : dx0, DYRE, DYIM, nr1, ni1);
            soa_bfly(re[J2], im[J2], y2r, y2i, CX, P2 ? cy1 : cy0, P2 ? cy0 : cy1, P2 ? dx1 : dx0, DYRE, DYIM, nr2, ni2);
            re[J] = nr1; im[J] = ni1; re[J2] = nr2; im[J2] = ni2;
        }
        loopC<MLO4, ALO4, J + 1>(re, im, CX, cy0, cy1, dx0, dx1, DYRE, DYIM);
    }
}

// Case D: lane bits only (partner via shuffle, optional half swap)
template<unsigned MHI, unsigned MB4, unsigned ALO4, int J>
__device__ __forceinline__ void loopD(u64* re, u64* im, u64 CX, u64 cy0, u64 cy1,
                                      u64 dx0, u64 dx1, u64 DYRE, u64 DYIM) {
    if constexpr (J < 16) {
        constexpr int P = parity(ALO4 & (unsigned)J);
        u64 yr = shfl64_xor(re[J], (int)MHI);
        u64 yi = shfl64_xor(im[J], (int)MHI);
        if constexpr (MB4) { yr = swap2(yr); yi = swap2(yi); }
        u64 nr, ni;
        soa_bfly(re[J], im[J], yr, yi, CX, P ? cy1 : cy0, P ? cy0 : cy1, P ? dx1 : dx0, DYRE, DYIM, nr, ni);
        re[J] = nr; im[J] = ni;
        loopD<MHI, MB4, ALO4, J + 1>(re, im, CX, cy0, cy1, dx0, dx1, DYRE, DYIM);
    }
}

// Case F: lane + local bits
template<unsigned MLO4, unsigned MB4, unsigned MHI, unsigned ALO4, int J>
__device__ __forceinline__ void loopF(u64* re, u64* im, u64 CX, u64 cy0, u64 cy1,
                                      u64 dx0, u64 dx1, u64 DYRE, u64 DYIM) {
    if constexpr (J < 16) {
        constexpr unsigned LOW = MLO4 & (0u - MLO4);
        if constexpr ((J & (int)LOW) == 0) {
            constexpr int J2 = J ^ (int)MLO4;
            constexpr int P  = parity(ALO4 & (unsigned)J);
            constexpr int P2 = parity(ALO4 & (unsigned)J2);
            u64 y1r = shfl64_xor(re[J2], (int)MHI);
            u64 y1i = shfl64_xor(im[J2], (int)MHI);
            u64 y2r = shfl64_xor(re[J],  (int)MHI);
            u64 y2i = shfl64_xor(im[J],  (int)MHI);
            if constexpr (MB4) {
                y1r = swap2(y1r); y1i = swap2(y1i);
                y2r = swap2(y2r); y2i = swap2(y2i);
            }
            u64 nr1, ni1, nr2, ni2;
            soa_bfly(re[J],  im[J],  y1r, y1i, CX, P  ? cy1 : cy0, P  ? cy0 : cy1, P  ? dx1 : dx0, DYRE, DYIM, nr1, ni1);
            soa_bfly(re[J2], im[J2], y2r, y2i, CX, P2 ? cy1 : cy0, P2 ? cy0 : cy1, P2 ? dx1 : dx0, DYRE, DYIM, nr2, ni2);
            re[J] = nr1; im[J] = ni1; re[J2] = nr2; im[J2] = ni2;
        }
        loopF<MLO4, MB4, MHI, ALO4, J + 1>(re, im, CX, cy0, cy1, dx0, dx1, DYRE, DYIM);
    }
}

template<int L, int W>
__device__ __forceinline__ void apply_gate(u64* re, u64* im,
                                           const float2* __restrict__ gm, int lane) {
    constexpr unsigned m    = MK2.pm[L][W];
    constexpr unsigned a    = MK2.am[L][W];
    constexpr unsigned mlo4 = m & 15u;
    constexpr unsigned mb4  = (m >> 4) & 1u;
    constexpr unsigned mhi  = (m >> 5) & 31u;
    constexpr unsigned alo4 = a & 15u;
    constexpr unsigned ab4  = (a >> 4) & 1u;
    constexpr unsigned ahi  = (a >> 5) & 31u;
    float2 g00 = gm[((L + 1) * 10 + W) * 4 + 0];
    float2 g01 = gm[((L + 1) * 10 + W) * 4 + 1];
    float cx = g00.x, cy = g00.y, dx = g01.x, dy = g01.y;
    u64 CX   = pack2(cx, cx);
    u64 CY0  = pack2(-cy, ab4 ? cy : -cy);   // multiplies Xi in out_re, parity-0 lo
    u64 DX0  = pack2(dx, ab4 ? -dx : dx);    // multiplies Y in both, parity-0 lo
    u64 DYRE = pack2(-dy, -dy);
    u64 DYIM = pack2(dy, dy);
    constexpr u64 SGN = 0x8000000080000000ull;
    u64 CY1 = CY0 ^ SGN;
    u64 DX1 = DX0 ^ SGN;
    int plane = (int)(__popc(ahi & (unsigned)lane) & 1);
    u64 cy0 = plane ? CY1 : CY0, cy1 = plane ? CY0 : CY1;
    u64 dx0 = plane ? DX1 : DX0, dx1 = plane ? DX0 : DX1;
    if constexpr (mhi == 0u && mb4 == 0u) {
        loopA<mlo4, alo4, 0>(re, im, CX, cy0, cy1, dx0, dx1, DYRE, DYIM);
    } else if constexpr (mhi == 0u && mlo4 == 0u) {
        loopB<alo4, 0>(re, im, CX, cy0, cy1, dx0, dx1, DYRE, DYIM);
    } else if constexpr (mhi == 0u) {
        loopC<mlo4, alo4, 0>(re, im, CX, cy0, cy1, dx0, dx1, DYRE, DYIM);
    } else if constexpr (mlo4 == 0u) {
        loopD<mhi, mb4, alo4, 0>(re, im, CX, cy0, cy1, dx0, dx1, DYRE, DYIM);
    } else {
        loopF<mlo4, mb4, mhi, alo4, 0>(re, im, CX, cy0, cy1, dx0, dx1, DYRE, DYIM);
    }
}

template<int G>
__device__ __forceinline__ void run_gates(u64* re, u64* im,
                                          const float2* __restrict__ gm, int lane) {
    if constexpr (G < 3 * NT) {
        apply_gate<G / NT, G % NT>(re, im, gm, lane);
        run_gates<G + 1>(re, im, gm, lane);
    }
}

// ================= measurement: packed |amp|^2 + packed FWHT =================
template<int K, int J>
__device__ __forceinline__ void fwht_stage_p(u64* pp, u64 ONE, u64 NEG) {
    if constexpr (J < 16) {
        if constexpr ((J & (1 << K)) == 0) {
            constexpr int J2 = J | (1 << K);
            u64 a = pp[J], b = pp[J2];
            pp[J]  = f2fma(ONE, b, a);
            pp[J2] = f2fma(NEG, b, a);
        }
        fwht_stage_p<K, J + 1>(pp, ONE, NEG);
    }
}
template<int K>
__device__ __forceinline__ void fwht_p(u64* pp, u64 ONE, u64 NEG) {
    if constexpr (K < 4) {
        fwht_stage_p<K, 0>(pp, ONE, NEG);
        fwht_p<K + 1>(pp, ONE, NEG);
    }
}
template<int W>
__device__ __forceinline__ void meas_from_p(const u64* pp, float* res, int lane) {
    if constexpr (W < NT) {
        constexpr unsigned z   = MK2.zm[W];
        constexpr unsigned idx = z & 15u;
        constexpr unsigned b4  = (z >> 4) & 1u;
        constexpr unsigned zhi = (z >> 5) & 31u;
        float2 v = unpack2(pp[idx]);
        float acc = b4 ? (v.x - v.y) : (v.x + v.y);
        if ((int)(__popc(zhi & (unsigned)lane) & 1)) acc = -acc;
        res[W] = acc;
        meas_from_p<W + 1>(pp, res, lane);
    }
}

// compile-time posq gather of embedding factors into position order
template<int P>
__device__ __forceinline__ void gather_factors(float2* fa, float2* fb, float2 va, float2 vb) {
    if constexpr (P < NT) {
        constexpr int q = MK2.posq[P];
        fa[P].x = __shfl_sync(0xffffffffu, va.x, q);
        fa[P].y = __shfl_sync(0xffffffffu, va.y, q);
        fb[P].x = __shfl_sync(0xffffffffu, vb.x, q);
        fb[P].y = __shfl_sync(0xffffffffu, vb.y, q);
        gather_factors<P + 1>(fa, fb, va, vb);
    }
}

// ================= 3-qubit register circuit =================
__device__ __forceinline__ float2 cadd3(float2 a, float2 b) {
    return make_float2(a.x + b.x, a.y + b.y);
}
__device__ __forceinline__ void run3(float x0, float x1, float x2,
                                     const float2* __restrict__ M, float E[3]) {
    float c[3], s[3];
    __sincosf(0.5f * x0, &s[0], &c[0]);
    __sincosf(0.5f * x1, &s[1], &c[1]);
    __sincosf(0.5f * x2, &s[2], &c[2]);
    float2 a[8];
#pragma unroll
    for (int i = 0; i < 8; i++) {
        float v = ((i >> 2) & 1 ? s[0] : c[0]) *
                  ((i >> 1) & 1 ? s[1] : c[1]) *
                  ((i      ) & 1 ? s[2] : c[2]);
        a[i] = make_float2(v, 0.f);
    }
#pragma unroll
    for (int l = 0; l < 4; l++) {
#pragma unroll
        for (int w = 0; w < 3; w++) {
            const float2* m = M + (l * 3 + w) * 4;
            const int p = 2 - w;
#pragma unroll
            for (int i0 = 0; i0 < 8; i0++) {
                if (i0 & (1 << p)) continue;
                int i1 = i0 | (1 << p);
                float2 A = a[i0], B = a[i1];
                a[i0] = cadd3(cmulf(m[0], A), cmulf(m[1], B));
                a[i1] = cadd3(cmulf(m[2], A), cmulf(m[3], B));
            }
        }
        const int r = (l & 1) + 1;
#pragma unroll
        for (int i = 0; i < 3; i++) {
            int pc = 2 - i;
            int pt = 2 - ((i + r) % 3);
#pragma unroll
            for (int idx = 0; idx < 8; idx++) {
                if (((idx >> pc) & 1) && !((idx >> pt) & 1)) {
                    int j = idx | (1 << pt);
                    float2 t = a[idx]; a[idx] = a[j]; a[j] = t;
                }
            }
        }
    }
    E[0] = E[1] = E[2] = 0.f;
#pragma unroll
    for (int i = 0; i < 8; i++) {
        float p = a[i].x * a[i].x + a[i].y * a[i].y;
        E[0] += (i & 4) ? -p : p;
        E[1] += (i & 2) ? -p : p;
        E[2] += (i & 1) ? -p : p;
    }
}

// ================= prep: Rot matrices =================
__global__ void prep_kernel(const float* __restrict__ t_stem,
                            const float* __restrict__ t_attn,
                            const float* __restrict__ t_ffn,
                            const float* __restrict__ t_red) {
    int i = blockIdx.x * blockDim.x + threadIdx.x;
    if (i < 960) {
        const float* a;
        if (i < 120)      a = t_stem + i * 3;
        else if (i < 600) a = t_attn + (i - 120) * 3;
        else if (i < 840) a = t_ffn  + (i - 600) * 3;
        else              a = t_red  + (i - 840) * 3;
        float phi = a[0], th = a[1], om = a[2];
        float c, s, cp, sp, cm, sm;
        sincosf(0.5f * th, &s, &c);
        sincosf(0.5f * (phi + om), &sp, &cp);
        sincosf(0.5f * (phi - om), &sm, &cm);
        float2* m = &g_mats[i * 4];
        m[0] = make_float2( cp * c, -sp * c);
        m[1] = make_float2(-cm * s, -sm * s);
        m[2] = make_float2( cm * s, -sm * s);
        m[3] = make_float2( cp * c,  sp * c);
    }
}

// ================= stem =================
__global__ void stem_kernel(const float* __restrict__ x) {
    int i = blockIdx.x * blockDim.x + threadIdx.x;
    int t = i >> 10, b = i & 1023;
    float E[3];
    run3(x[b * 30 + 3 * t], x[b * 30 + 3 * t + 1], x[b * 30 + 3 * t + 2],
         g_mats + (t * 12) * 4, E);
#pragma unroll
    for (int k = 0; k < 3; k++) g_H[b * 30 + 3 * t + k] = E[k];
}

// ================= attention: warp-resident 10-qubit simulator (SoA) ==========
__global__ void __launch_bounds__(128) attn_kernel(int lay) {
    const int wid  = blockIdx.x * 4 + (threadIdx.x >> 5);
    const int lane = threadIdx.x & 31;
    const int b  = wid & 1023;
    const int hg = wid >> 10;
    const int h  = hg / 3, g = hg % 3;
    const float2* gm = g_mats + (120 + ((lay * 2 + h) * 3 + g) * 40) * 4;

    // ---- init: product state of V_q|0>, V_q = Rot(layer0,q) * RY(x_q) ----
    float2 va, vb;
    {
        int q = (lane < NT) ? lane : 0;
        float ang = (lane < NT) ? g_H[b * 30 + 3 * lane + g] : 0.f;
        float c, s;
        __sincosf(0.5f * ang, &s, &c);
        float2 g00 = gm[q * 4 + 0];
        float2 g01 = gm[q * 4 + 1];
        va = make_float2( g00.x * c + g01.x * s,  g00.y * c + g01.y * s);
        vb = make_float2(-g01.x * c + g00.x * s,  g01.y * c - g00.y * s);
    }
    float2 fa[NT], fb[NT];
    gather_factors<0>(fa, fb, va, vb);
    float2 lf = (lane & 1) ? fb[5] : fa[5];
#pragma unroll
    for (int p = 6; p < NT; p++)
        lf = cmulf(lf, ((lane >> (p - 5)) & 1) ? fb[p] : fa[p]);
    float2 T[32];
    T[0] = cmulf(lf, fa[0]);
    T[1] = cmulf(lf, fb[0]);
#pragma unroll
    for (int k = 1; k < 5; k++) {
#pragma unroll
        for (int j = 0; j < 16; j++) {
            if (j < (1 << k)) {
                T[j | (1 << k)] = cmulf(T[j], fb[k]);
                T[j]            = cmulf(T[j], fa[k]);
            }
        }
    }
    // SoA pack: vector bit = local position 4 (amp j with amp j+16)
    u64 re[16], im[16];
#pragma unroll
    for (int j = 0; j < 16; j++) {
        re[j] = pack2(T[j].x, T[j + 16].x);
        im[j] = pack2(T[j].y, T[j + 16].y);
    }

    // ---- layers 1..3 (conjugated gates, compile-time masks) ----
    run_gates<0>(re, im, gm, lane);

    // ---- measurement: packed |amp|^2, packed FWHT, bit4 combine ----
    u64 pp[16];
#pragma unroll
    for (int j = 0; j < 16; j++)
        pp[j] = f2fma(re[j], re[j], f2mul(im[j], im[j]));
    {
        u64 ONE = pack2(1.f, 1.f);
        u64 NEG = pack2(-1.f, -1.f);
        fwht_p<0>(pp, ONE, NEG);
    }
    float res[NT];
    meas_from_p<0>(pp, res, lane);
#pragma unroll
    for (int w = 0; w < NT; w++) {
#pragma unroll
        for (int off = 16; off; off >>= 1)
            res[w] += __shfl_xor_sync(0xffffffffu, res[w], off);
    }
    if (lane == 0) {
#pragma unroll
        for (int w = 0; w < NT; w++)
            g_attn[b * 60 + h * 30 + 3 * w + g] = res[w];
    }
}

// ================= fused W_O projection + residual + FFN (layer 0) ==========
__global__ void wo_ffn_kernel(const float* __restrict__ W_O, int lay) {
    int gt = blockIdx.x * blockDim.x + threadIdx.x;
    int b = gt >> 5, lane = gt & 31;

    float newH = 0.f;
    if (lane < 30) {
        const float4* wrow = (const float4*)(W_O + (lay * 30 + lane) * 60);
        const float4* arow = (const float4*)(g_attn + b * 60);
        float s0 = 0.f, s1 = 0.f, s2 = 0.f, s3 = 0.f;
#pragma unroll
        for (int k = 0; k < 15; k++) {
            float4 w4 = wrow[k];
            float4 a4 = arow[k];
            s0 = fmaf(a4.x, w4.x, s0);
            s1 = fmaf(a4.y, w4.y, s1);
            s2 = fmaf(a4.z, w4.z, s2);
            s3 = fmaf(a4.w, w4.w, s3);
        }
        newH = g_H[b * 30 + lane] + ((s0 + s1) + (s2 + s3));
    }
    __syncwarp();

    int f0 = 3 * lane, f1 = f0 + 1, f2 = f0 + 2;
    float in0 = __shfl_sync(0xffffffffu, newH, (3 * (f0 % 10) + f0 / 10) & 31);
    float in1 = __shfl_sync(0xffffffffu, newH, (3 * (f1 % 10) + f1 / 10) & 31);
    float in2 = __shfl_sync(0xffffffffu, newH, (3 * (f2 % 10) + f2 / 10) & 31);
    if (lane >= 10) { in0 = 0.f; in1 = 0.f; in2 = 0.f; }
    int t = (lane < 10) ? lane : 0;
    float E[3];
    run3(in0, in1, in2, g_mats + (600 + (lay * 10 + t) * 12) * 4, E);

    float h0 = __shfl_sync(0xffffffffu, newH, (3 * lane) & 31);
    float h1 = __shfl_sync(0xffffffffu, newH, (3 * lane + 1) & 31);
    float h2 = __shfl_sync(0xffffffffu, newH, (3 * lane + 2) & 31);
    if (lane < 10) {
        g_H[b * 30 + 3 * lane + 0] = h0 + E[0];
        g_H[b * 30 + 3 * lane + 1] = h1 + E[1];
        g_H[b * 30 + 3 * lane + 2] = h2 + E[2];
    }
}

// ===== layer-1 W_O + residual + FFN + reduce + classification, fully fused ====
__global__ void wo_ffn_cls_kernel(const float* __restrict__ W_O,
                                  const float* __restrict__ Wc,
                                  const float* __restrict__ bc,
                                  float* __restrict__ out) {
    int gt = blockIdx.x * blockDim.x + threadIdx.x;
    int b = gt >> 5, lane = gt & 31;
    const int lay = 1;

    float newH = 0.f;
    if (lane < 30) {
        const float4* wrow = (const float4*)(W_O + (lay * 30 + lane) * 60);
        const float4* arow = (const float4*)(g_attn + b * 60);
        float s0 = 0.f, s1 = 0.f, s2 = 0.f, s3 = 0.f;
#pragma unroll
        for (int k = 0; k < 15; k++) {
            float4 w4 = wrow[k];
            float4 a4 = arow[k];
            s0 = fmaf(a4.x, w4.x, s0);
            s1 = fmaf(a4.y, w4.y, s1);
            s2 = fmaf(a4.z, w4.z, s2);
            s3 = fmaf(a4.w, w4.w, s3);
        }
        newH = g_H[b * 30 + lane] + ((s0 + s1) + (s2 + s3));
    }
    __syncwarp();

    int f0 = 3 * lane, f1 = f0 + 1, f2 = f0 + 2;
    float in0 = __shfl_sync(0xffffffffu, newH, (3 * (f0 % 10) + f0 / 10) & 31);
    float in1 = __shfl_sync(0xffffffffu, newH, (3 * (f1 % 10) + f1 / 10) & 31);
    float in2 = __shfl_sync(0xffffffffu, newH, (3 * (f2 % 10) + f2 / 10) & 31);
    if (lane >= 10) { in0 = 0.f; in1 = 0.f; in2 = 0.f; }
    int t = (lane < 10) ? lane : 0;
    float E[3];
    run3(in0, in1, in2, g_mats + (600 + (lay * 10 + t) * 12) * 4, E);

    float h0 = __shfl_sync(0xffffffffu, newH, (3 * lane) & 31);
    float h1 = __shfl_sync(0xffffffffu, newH, (3 * lane + 1) & 31);
    float h2 = __shfl_sync(0xffffffffu, newH, (3 * lane + 2) & 31);

    float red = 0.f;
    {
        float hv0 = h0 + E[0], hv1 = h1 + E[1], hv2 = h2 + E[2];
        float R[3];
        run3(hv0, hv1, hv2, g_mats + (840 + t * 12) * 4, R);
        if (lane < 10) red = R[0];
    }
    float rv[10];
#pragma unroll
    for (int tt = 0; tt < 10; tt++)
        rv[tt] = __shfl_sync(0xffffffffu, red, tt);
    if (lane < 10) {
        float s = bc[lane];
#pragma unroll
        for (int tt = 0; tt < 10; tt++) s = fmaf(rv[tt], Wc[lane * 10 + tt], s);
        out[b * 10 + lane] = s;
    }
}

// ================= launch =================
extern "C" void kernel_launch(void* const* d_in, const int* in_sizes, int n_in,
                              void* d_out, int out_size) {
    const float* x_      = (const float*)d_in[0];
    const float* t_stem  = (const float*)d_in[1];
    const float* t_attn  = (const float*)d_in[2];
    const float* W_O     = (const float*)d_in[3];
    const float* t_ffn   = (const float*)d_in[4];
    const float* t_red   = (const float*)d_in[5];
    const float* W_cls   = (const float*)d_in[6];
    const float* b_cls   = (const float*)d_in[7];
    float* out = (float*)d_out;

    prep_kernel<<<4, 256>>>(t_stem, t_attn, t_ffn, t_red);
    stem_kernel<<<40, 256>>>(x_);
    attn_kernel<<<1536, 128>>>(0);
    wo_ffn_kernel<<<128, 256>>>(W_O, 0);
    attn_kernel<<<1536, 128>>>(1);
    wo_ffn_cls_kernel<<<128, 256>>>(W_O, W_cls, b_cls, out);
}